// round 13
// baseline (speedup 1.0000x reference)
#include <cuda_runtime.h>
#include <math.h>
#include <stdint.h>

#define BB 16
#define LL 512
#define DD 128
#define EPSN 1e-12f
#define TL 16
#define CS 4
#define RK 32
#define PP 132

#define A1 0.9f
#define A2 0.81f
#define A3 0.729f

// Scratch (device globals; no allocation allowed)
__device__ float g_kphi[BB * LL * DD];
__device__ float g_qphi[BB * LL * DD];
__device__ float g_y[BB * LL * DD];
__device__ float g_WqT[DD * DD];
__device__ float g_WkT[DD * DD];
__device__ float g_WoT[DD * DD];

// ---------------- PTX helpers ----------------
__device__ __forceinline__ uint32_t smem_u32(const void* p) {
    uint32_t a;
    asm("{ .reg .u64 t; cvta.to.shared.u64 t, %1; cvt.u32.u64 %0, t; }" : "=r"(a) : "l"(p));
    return a;
}
__device__ __forceinline__ uint32_t cluster_rank() {
    uint32_t r;
    asm("mov.u32 %0, %%cluster_ctarank;" : "=r"(r));
    return r;
}
#define CARRIVE() asm volatile("barrier.cluster.arrive.aligned;" ::: "memory")
#define CWAIT()   asm volatile("barrier.cluster.wait.aligned;" ::: "memory")

__device__ __forceinline__ void pst(uint32_t addr, float v) {
    asm volatile("st.shared::cluster.b32 [%0], %1;" :: "r"(addr), "r"(__float_as_uint(v)) : "memory");
}

// ---------------- transpose Wq/Wk/Wout ----------------
__global__ void transpose_k(const float* __restrict__ Wq,
                            const float* __restrict__ Wk,
                            const float* __restrict__ Wo) {
    __shared__ float tb[32][33];
    const float* src = blockIdx.z == 0 ? Wq : (blockIdx.z == 1 ? Wk : Wo);
    float* dst = blockIdx.z == 0 ? g_WqT : (blockIdx.z == 1 ? g_WkT : g_WoT);
    int tx = threadIdx.x, ty = threadIdx.y;
    int bx = blockIdx.x * 32, by = blockIdx.y * 32;
#pragma unroll
    for (int j = 0; j < 32; j += 8) tb[ty + j][tx] = src[(by + ty + j) * DD + bx + tx];
    __syncthreads();
#pragma unroll
    for (int j = 0; j < 32; j += 8) dst[(bx + ty + j) * DD + by + tx] = tb[tx][ty + j];
}

// ---------------- prepass ----------------
__global__ __launch_bounds__(DD)
void prepass_kernel(const float* __restrict__ x,
                    const float* __restrict__ P0,
                    const float* __restrict__ log_gain,
                    const float* __restrict__ coeffs) {
    const int b = blockIdx.y, l0 = blockIdx.x * TL;
    const int e = threadIdx.x;
    __shared__ float xs[TL][DD];
    __shared__ float qs[TL][DD];
    __shared__ float rn[TL];

    const float* xp = x + (b * LL + l0) * DD;
#pragma unroll
    for (int tt = 0; tt < TL; ++tt) xs[tt][e] = xp[tt * DD + e];
    __syncthreads();

    float qa[TL], ka[TL];
#pragma unroll
    for (int tt = 0; tt < TL; ++tt) { qa[tt] = 0.f; ka[tt] = 0.f; }
    for (int d = 0; d < DD; ++d) {
        float wq = g_WqT[d * DD + e], wk = g_WkT[d * DD + e];
#pragma unroll
        for (int tt = 0; tt < TL; ++tt) {
            float xv = xs[tt][d];
            qa[tt] += xv * wq;
            ka[tt] += xv * wk;
        }
    }
#pragma unroll
    for (int tt = 0; tt < TL; ++tt) qs[tt][e] = qa[tt];
    __syncthreads();
#pragma unroll
    for (int tt = 0; tt < TL; ++tt) xs[tt][e] = ka[tt] * ka[tt];
    __syncthreads();
    {
        const int w = e >> 5, l = e & 31;
#pragma unroll
        for (int i = 0; i < 4; ++i) {
            int tt = w * 4 + i;
            float v = xs[tt][l] + xs[tt][l + 32] + xs[tt][l + 64] + xs[tt][l + 96];
#pragma unroll
            for (int o = 16; o; o >>= 1) v += __shfl_xor_sync(0xffffffffu, v, o);
            if (l == 0) rn[tt] = 1.0f / fmaxf(sqrtf(v), EPSN);
        }
    }
    __syncthreads();

    float qp[TL];
#pragma unroll
    for (int tt = 0; tt < TL; ++tt) qp[tt] = 0.f;
    for (int d = 0; d < DD; ++d) {
        float p = P0[d * DD + e];
#pragma unroll
        for (int tt = 0; tt < TL; ++tt) qp[tt] += qs[tt][d] * p;
    }
    const float gain = expf(log_gain[e]);
    const float c0 = coeffs[0], c1 = coeffs[1];
#pragma unroll
    for (int tt = 0; tt < TL; ++tt) {
        float kn = ka[tt] * rn[tt];
        g_kphi[(b * LL + l0 + tt) * DD + e] = c0 * kn + c1 * kn * kn;
        float qv = tanhf(gain * qp[tt]);
        g_qphi[(b * LL + l0 + tt) * DD + e] = c0 * qv + c1 * qv * qv;
    }
}

// ---------------- postpass ----------------
__global__ __launch_bounds__(DD)
void postpass_kernel(const float* __restrict__ bout, float* __restrict__ out) {
    const int b = blockIdx.y, l0 = blockIdx.x * TL;
    const int e = threadIdx.x;
    __shared__ float ys[TL][DD];
#pragma unroll
    for (int tt = 0; tt < TL; ++tt) ys[tt][e] = g_y[(b * LL + l0 + tt) * DD + e];
    __syncthreads();
    float acc[TL];
#pragma unroll
    for (int tt = 0; tt < TL; ++tt) acc[tt] = 0.f;
    for (int d = 0; d < DD; ++d) {
        float w = g_WoT[d * DD + e];
#pragma unroll
        for (int tt = 0; tt < TL; ++tt) acc[tt] += ys[tt][d] * w;
    }
    const float bo = bout[e];
#pragma unroll
    for (int tt = 0; tt < TL; ++tt) out[(b * LL + l0 + tt) * DD + e] = acc[tt] + bo;
}

// ---------------- scan ----------------
// smem float offsets
#define OFF_S   0                          // 32*PP
#define OFF_Tm  4224                       // 32*PP
#define OFF_S0  8448                       // 128*PP (init only)
#define OFF_EB  25344                      // [2][128]
#define OFF_VB  25600
#define OFF_WP  25856                      // [2][4][128]
#define OFF_ZP  26880
#define OFF_WA  27904                      // [128]
#define OFF_ZA  28032
#define OFF_UA  28160                      // [32] u2 own rows
#define OFF_KB  28192                      // [2][128]
#define OFF_QS  28448
#define OFF_XN  28576                      // [2][128]
#define OFF_EN  28832                      // [32]
#define OFF_VNL 28864
#define OFF_SC  28896
#define OFF_SCR 28904                      // [256] init scratch
#define SCAN_FLOATS 29160
#define SCAN_SMEM (SCAN_FLOATS * 4)

#define UPD(X, idx) { \
    float Snv = A1 * S4.X + e_r * kc.X; \
    float Tnv = A2 * T4.X + alpha * ec.X + beta * vc.X; \
    float Unv = A3 * u[idx] + p_r * kc.X + cwv * wc.X + czv * zc.X; \
    u[idx] = Unv; \
    float mnv = 0.99f * m[idx] - cS * Snv + cU * Unv; \
    m[idx] = mnv; \
    accY += mnv * qc.X; accP += mnv * kn.X; accV += Snv * kn.X; \
    S4.X = Snv; T4.X = Tnv; }

__global__ __launch_bounds__(256, 1)
void scan_kernel(const float* __restrict__ x,
                 const float* __restrict__ M0,
                 const float* __restrict__ S0) {
    extern __shared__ float sm[];
    float* Ss   = sm + OFF_S;
    float* Ts   = sm + OFF_Tm;
    float* S0s  = sm + OFF_S0;
    float* eb   = sm + OFF_EB;
    float* vbuf = sm + OFF_VB;
    float* wa   = sm + OFF_WA;
    float* za   = sm + OFF_ZA;
    float* ua   = sm + OFF_UA;
    float* kb   = sm + OFF_KB;
    float* qs   = sm + OFF_QS;
    float* xn   = sm + OFF_XN;
    float* en   = sm + OFF_EN;
    float* vnl  = sm + OFF_VNL;
    float* sc   = sm + OFF_SC;
    float* scr  = sm + OFF_SCR;

    const uint32_t sbase = smem_u32(sm);
    const int tid = threadIdx.x;
    const int w = tid >> 5, lane = tid & 31;
    const int lr = (w << 2) + (lane >> 3);   // owned local row (0..31)
    const int sg = lane & 7;                 // 16-col segment
    const int c0 = sg << 4;
    const uint32_t rk = cluster_rank();
    const int batch = blockIdx.x >> 2;
    const int rbase = (int)rk * RK;

    uint32_t pb[4];
#pragma unroll
    for (int i = 0; i < 4; ++i)
        asm("mapa.shared::cluster.u32 %0, %1, %2;" : "=r"(pb[i]) : "r"(sbase), "r"(i));

    const float* kphi = g_kphi + batch * LL * DD;
    const float* qphi = g_qphi + batch * LL * DD;
    const float* xb = x + batch * LL * DD;
    float* yb = g_y + batch * LL * DD;

    // ---------- init ----------
    for (int i = tid; i < DD * DD; i += 256) {
        int r = i >> 7, c = i & 127;
        S0s[r * PP + c] = S0[i];
    }
    if (tid < DD) {
        kb[tid] = kphi[tid];             // k_0
        kb[DD + tid] = kphi[DD + tid];   // k_1
        qs[tid] = qphi[tid];             // q_0
        xn[tid] = xb[DD + tid];          // x_1 (slot p=0)
    }
    float m[16], u[16];
#pragma unroll
    for (int j = 0; j < 16; ++j) m[j] = M0[(rbase + lr) * DD + c0 + j];
    __syncthreads();

    // sigma0
    {
        float ps = 0.f;
        for (int i = tid; i < DD * DD; i += 256) {
            int r = i >> 7, c = i & 127;
            float v = S0s[r * PP + c];
            ps += v * v;
        }
        scr[tid] = ps;
    }
    __syncthreads();
    if (tid < 32) {
        float s = 0.f;
#pragma unroll
        for (int j = 0; j < 8; ++j) s += scr[tid * 8 + j];
#pragma unroll
        for (int o = 16; o; o >>= 1) s += __shfl_xor_sync(0xffffffffu, s, o);
        if (tid == 0) sc[3] = s;
    }
    __syncthreads();
    float sig = sc[3];

    // S strip
    for (int i = tid; i < RK * DD; i += 256) {
        int r = i >> 7, c = i & 127;
        Ss[r * PP + c] = S0s[(rbase + r) * PP + c];
    }
    __syncthreads();
    // T strip + U regs
    if (sig != 0.0f) {
#pragma unroll 1
        for (int j = 0; j < 16; ++j) {
            int c = c0 + j;
            float a = 0.f;
            for (int k = 0; k < DD; ++k)
                a += S0s[(rbase + lr) * PP + k] * S0s[c * PP + k];
            Ts[lr * PP + c] = a;
        }
        __syncthreads();
#pragma unroll 1
        for (int j = 0; j < 16; ++j) {
            int c = c0 + j;
            float a = 0.f;
            for (int k = 0; k < DD; ++k)
                a += Ts[lr * PP + k] * S0s[k * PP + c];
            u[j] = a;
        }
    } else {
        for (int i = tid; i < RK * DD; i += 256) {
            int r = i >> 7, c = i & 127;
            Ts[r * PP + c] = 0.f;
        }
#pragma unroll
        for (int j = 0; j < 16; ++j) u[j] = 0.f;
    }
    __syncthreads();

    // e0 = M0 k0 - x0 ; v0 = S0 k0  (in-warp over 8-lane row groups)
    {
        float pr = 0.f, vv = 0.f;
        const int base = lr * PP + c0;
#pragma unroll
        for (int j = 0; j < 16; ++j) {
            float kc = kb[c0 + j];
            pr += m[j] * kc;
            vv += Ss[base + j] * kc;
        }
#pragma unroll
        for (int o = 4; o; o >>= 1) {
            pr += __shfl_xor_sync(0xffffffffu, pr, o);
            vv += __shfl_xor_sync(0xffffffffu, vv, o);
        }
        if (sg == 0) {
            float e = pr - xb[rbase + lr];
            en[lr] = e; vnl[lr] = vv;
            uint32_t eo = (OFF_EB + rbase + lr) * 4;
            uint32_t vo = (OFF_VB + rbase + lr) * 4;
#pragma unroll
            for (int i = 0; i < 4; ++i) { pst(pb[i] + eo, e); pst(pb[i] + vo, vv); }
        }
    }
    __syncthreads();
    // w0/z0 column partials (1 thread per column per quantity)
    if (tid < 128) {
        int c = tid;
        float wv = 0.f;
#pragma unroll 8
        for (int r = 0; r < 32; ++r) wv += Ss[r * PP + c] * en[r];
        uint32_t wo = (OFF_WP + (int)rk * 128 + c) * 4;
#pragma unroll
        for (int i = 0; i < 4; ++i) pst(pb[i] + wo, wv);
    } else {
        int c = tid - 128;
        float zv = 0.f;
#pragma unroll 8
        for (int r = 0; r < 32; ++r) zv += Ss[r * PP + c] * vnl[r];
        uint32_t zo = (OFF_ZP + (int)rk * 128 + c) * 4;
#pragma unroll
        for (int i = 0; i < 4; ++i) pst(pb[i] + zo, zv);
    }
    CARRIVE();

    // ---------- main loop ----------
    for (int t = 0; t < LL; ++t) {
        const int p = t & 1;
        float rq = 0.f, rx = 0.f, rkk = 0.f;
        if (tid < 128) {   // prefetch; hides under CWAIT
            int t1 = (t + 1 < LL) ? t + 1 : LL - 1;
            int t2 = (t + 2 < LL) ? t + 2 : LL - 1;
            rq = qphi[t1 * DD + tid];
            rx = xb[t2 * DD + tid];
            rkk = kphi[t2 * DD + tid];
        }
        CWAIT();

        // phase 1a: assemble w/z from 4 CTA partials
        {
            int c = tid & 127;
            int srco = (tid < 128 ? OFF_WP : OFF_ZP) + p * 512 + c;
            float s = sm[srco] + sm[srco + 128] + sm[srco + 256] + sm[srco + 384];
            sm[(tid < 128 ? OFF_WA : OFF_ZA) + c] = s;
        }
        // phase 1b: u2[lr] = T_strip[lr,:] . e  (local row-dot; T symmetric)
        {
            const float* ecur = eb + p * DD;
            float s = 0.f;
            const int base = lr * PP + c0;
#pragma unroll
            for (int j4 = 0; j4 < 4; ++j4) {
                float4 t4 = *(const float4*)&Ts[base + j4 * 4];
                float4 e4 = *(const float4*)&ecur[c0 + j4 * 4];
                s += t4.x * e4.x + t4.y * e4.y + t4.z * e4.z + t4.w * e4.w;
            }
#pragma unroll
            for (int o = 4; o; o >>= 1) s += __shfl_xor_sync(0xffffffffu, s, o);
            if (sg == 0) ua[lr] = s;
        }
        // phase 1c: scalars kappa, eps, nu
        if (w < 3) {
            const float* va = (w == 0) ? (kb + p * DD) : (eb + p * DD);
            const float* vb2 = (w == 2) ? (vbuf + p * DD) : va;
            float s = 0.f;
#pragma unroll
            for (int i2 = 0; i2 < 4; ++i2) { int idx = lane + i2 * 32; s += va[idx] * vb2[idx]; }
#pragma unroll
            for (int o = 16; o; o >>= 1) s += __shfl_xor_sync(0xffffffffu, s, o);
            if (lane == 0) sc[w] = s;
        }
        __syncthreads();

        const float kappa = sc[0], eps = sc[1], nu = sc[2];
        sig = A2 * sig + 2.0f * A1 * nu + kappa * eps;
        const float nrm = sqrtf(sig) + 1e-6f;
        const float cS = 0.015f / nrm;
        const float cU = 0.005f / (nrm * nrm * nrm);

        // phase 2: fused strip update + in-warp matvecs + e/v production
        {
            const float e_r = eb[p * DD + rbase + lr];
            const float v_r = vbuf[p * DD + rbase + lr];
            const float u2r = ua[lr];
            const float alpha = A1 * v_r + kappa * e_r;
            const float beta = A1 * e_r;
            const float p_r = A2 * u2r + A1 * eps * v_r + (A1 * nu + kappa * eps) * e_r;
            const float cwv = A2 * v_r + A1 * kappa * e_r;
            const float czv = A2 * e_r;
            const float* kcur = kb + p * DD;
            const float* knxp = kb + (p ^ 1) * DD;
            const float* ecol = eb + p * DD;
            const float* vcol = vbuf + p * DD;
            float accY = 0.f, accP = 0.f, accV = 0.f;
            const int base = lr * PP + c0;
#pragma unroll
            for (int j4 = 0; j4 < 4; ++j4) {
                const int c = c0 + j4 * 4;
                float4 kc = *(const float4*)&kcur[c];
                float4 ec = *(const float4*)&ecol[c];
                float4 vc = *(const float4*)&vcol[c];
                float4 wc = *(const float4*)&wa[c];
                float4 zc = *(const float4*)&za[c];
                float4 qc = *(const float4*)&qs[c];
                float4 kn = *(const float4*)&knxp[c];
                float4 S4 = *(float4*)&Ss[base + j4 * 4];
                float4 T4 = *(float4*)&Ts[base + j4 * 4];
                UPD(x, j4 * 4 + 0)
                UPD(y, j4 * 4 + 1)
                UPD(z, j4 * 4 + 2)
                UPD(w, j4 * 4 + 3)
                *(float4*)&Ss[base + j4 * 4] = S4;
                *(float4*)&Ts[base + j4 * 4] = T4;
            }
#pragma unroll
            for (int o = 4; o; o >>= 1) {
                accY += __shfl_xor_sync(0xffffffffu, accY, o);
                accP += __shfl_xor_sync(0xffffffffu, accP, o);
                accV += __shfl_xor_sync(0xffffffffu, accV, o);
            }
            if (sg == 0) {
                float e = accP - xn[p * DD + rbase + lr];
                yb[t * DD + rbase + lr] = accY;
                en[lr] = e;
                vnl[lr] = accV;
                if (t + 1 < LL) {
                    uint32_t eo = (OFF_EB + (p ^ 1) * DD + rbase + lr) * 4;
                    uint32_t vo = (OFF_VB + (p ^ 1) * DD + rbase + lr) * 4;
#pragma unroll
                    for (int i = 0; i < 4; ++i) { pst(pb[i] + eo, e); pst(pb[i] + vo, accV); }
                }
            }
        }
        __syncthreads();

        // phase 4: w/z column partials + staging + exchange
        if (t + 1 < LL) {
            if (tid < 128) {
                int c = tid;
                float wv = 0.f;
#pragma unroll 8
                for (int r = 0; r < 32; ++r) wv += Ss[r * PP + c] * en[r];
                uint32_t wo = (OFF_WP + (p ^ 1) * 512 + (int)rk * 128 + c) * 4;
#pragma unroll
                for (int i = 0; i < 4; ++i) pst(pb[i] + wo, wv);
                qs[c] = rq;
                xn[(p ^ 1) * DD + c] = rx;
                kb[p * DD + c] = rkk;
            } else {
                int c = tid - 128;
                float zv = 0.f;
#pragma unroll 8
                for (int r = 0; r < 32; ++r) zv += Ss[r * PP + c] * vnl[r];
                uint32_t zo = (OFF_ZP + (p ^ 1) * 512 + (int)rk * 128 + c) * 4;
#pragma unroll
                for (int i = 0; i < 4; ++i) pst(pb[i] + zo, zv);
            }
            CARRIVE();
        }
    }
}

// ---------------- harness entry ----------------
extern "C" void kernel_launch(void* const* d_in, const int* in_sizes, int n_in,
                              void* d_out, int out_size) {
    const float* x    = (const float*)d_in[0];
    const float* Wq   = (const float*)d_in[1];
    const float* Wk   = (const float*)d_in[2];
    const float* P0   = (const float*)d_in[3];
    const float* M0   = (const float*)d_in[4];
    const float* S0   = (const float*)d_in[5];
    const float* lg   = (const float*)d_in[6];
    const float* cf   = (const float*)d_in[7];
    const float* Wout = (const float*)d_in[8];
    const float* bout = (const float*)d_in[9];
    float* out = (float*)d_out;

    cudaFuncSetAttribute(scan_kernel, cudaFuncAttributeMaxDynamicSharedMemorySize, SCAN_SMEM);

    transpose_k<<<dim3(4, 4, 3), dim3(32, 8)>>>(Wq, Wk, Wout);
    prepass_kernel<<<dim3(LL / TL, BB), DD>>>(x, P0, lg, cf);

    cudaLaunchConfig_t cfg = {};
    cfg.gridDim = dim3(CS * BB, 1, 1);
    cfg.blockDim = dim3(256, 1, 1);
    cfg.dynamicSmemBytes = SCAN_SMEM;
    cfg.stream = 0;
    cudaLaunchAttribute attrs[1];
    attrs[0].id = cudaLaunchAttributeClusterDimension;
    attrs[0].val.clusterDim.x = CS;
    attrs[0].val.clusterDim.y = 1;
    attrs[0].val.clusterDim.z = 1;
    cfg.attrs = attrs;
    cfg.numAttrs = 1;
    cudaLaunchKernelEx(&cfg, scan_kernel, x, M0, S0);

    postpass_kernel<<<dim3(LL / TL, BB), DD>>>(bout, out);
}

// round 14
// speedup vs baseline: 2.0290x; 2.0290x over previous
#include <cuda_runtime.h>
#include <math.h>
#include <stdint.h>

#define BB 16
#define LL 512
#define DD 128
#define EPSN 1e-12f
#define TL 16
#define CS 4
#define RK 32
#define PP 132

#define A1 0.9f
#define A2 0.81f
#define A3 0.729f

// Scratch (device globals; no allocation allowed)
__device__ float g_kphi[BB * LL * DD];
__device__ float g_qphi[BB * LL * DD];
__device__ float g_y[BB * LL * DD];
__device__ float g_WqT[DD * DD];
__device__ float g_WkT[DD * DD];
__device__ float g_WoT[DD * DD];

// ---------------- PTX helpers ----------------
__device__ __forceinline__ uint32_t smem_u32(const void* p) {
    uint32_t a;
    asm("{ .reg .u64 t; cvta.to.shared.u64 t, %1; cvt.u32.u64 %0, t; }" : "=r"(a) : "l"(p));
    return a;
}
__device__ __forceinline__ uint32_t cluster_rank() {
    uint32_t r;
    asm("mov.u32 %0, %%cluster_ctarank;" : "=r"(r));
    return r;
}
#define CARRIVE() asm volatile("barrier.cluster.arrive.aligned;" ::: "memory")
#define CWAIT()   asm volatile("barrier.cluster.wait.aligned;" ::: "memory")

__device__ __forceinline__ void pst(uint32_t addr, float v) {
    asm volatile("st.shared::cluster.b32 [%0], %1;" :: "r"(addr), "r"(__float_as_uint(v)) : "memory");
}

// ---------------- transpose Wq/Wk/Wout ----------------
__global__ void transpose_k(const float* __restrict__ Wq,
                            const float* __restrict__ Wk,
                            const float* __restrict__ Wo) {
    __shared__ float tb[32][33];
    const float* src = blockIdx.z == 0 ? Wq : (blockIdx.z == 1 ? Wk : Wo);
    float* dst = blockIdx.z == 0 ? g_WqT : (blockIdx.z == 1 ? g_WkT : g_WoT);
    int tx = threadIdx.x, ty = threadIdx.y;
    int bx = blockIdx.x * 32, by = blockIdx.y * 32;
#pragma unroll
    for (int j = 0; j < 32; j += 8) tb[ty + j][tx] = src[(by + ty + j) * DD + bx + tx];
    __syncthreads();
#pragma unroll
    for (int j = 0; j < 32; j += 8) dst[(bx + ty + j) * DD + by + tx] = tb[tx][ty + j];
}

// ---------------- prepass ----------------
__global__ __launch_bounds__(DD)
void prepass_kernel(const float* __restrict__ x,
                    const float* __restrict__ P0,
                    const float* __restrict__ log_gain,
                    const float* __restrict__ coeffs) {
    const int b = blockIdx.y, l0 = blockIdx.x * TL;
    const int e = threadIdx.x;
    __shared__ float xs[TL][DD];
    __shared__ float qs[TL][DD];
    __shared__ float rn[TL];

    const float* xp = x + (b * LL + l0) * DD;
#pragma unroll
    for (int tt = 0; tt < TL; ++tt) xs[tt][e] = xp[tt * DD + e];
    __syncthreads();

    float qa[TL], ka[TL];
#pragma unroll
    for (int tt = 0; tt < TL; ++tt) { qa[tt] = 0.f; ka[tt] = 0.f; }
    for (int d = 0; d < DD; ++d) {
        float wq = g_WqT[d * DD + e], wk = g_WkT[d * DD + e];
#pragma unroll
        for (int tt = 0; tt < TL; ++tt) {
            float xv = xs[tt][d];
            qa[tt] += xv * wq;
            ka[tt] += xv * wk;
        }
    }
#pragma unroll
    for (int tt = 0; tt < TL; ++tt) qs[tt][e] = qa[tt];
    __syncthreads();
#pragma unroll
    for (int tt = 0; tt < TL; ++tt) xs[tt][e] = ka[tt] * ka[tt];
    __syncthreads();
    {
        const int w = e >> 5, l = e & 31;
#pragma unroll
        for (int i = 0; i < 4; ++i) {
            int tt = w * 4 + i;
            float v = xs[tt][l] + xs[tt][l + 32] + xs[tt][l + 64] + xs[tt][l + 96];
#pragma unroll
            for (int o = 16; o; o >>= 1) v += __shfl_xor_sync(0xffffffffu, v, o);
            if (l == 0) rn[tt] = 1.0f / fmaxf(sqrtf(v), EPSN);
        }
    }
    __syncthreads();

    float qp[TL];
#pragma unroll
    for (int tt = 0; tt < TL; ++tt) qp[tt] = 0.f;
    for (int d = 0; d < DD; ++d) {
        float p = P0[d * DD + e];
#pragma unroll
        for (int tt = 0; tt < TL; ++tt) qp[tt] += qs[tt][d] * p;
    }
    const float gain = expf(log_gain[e]);
    const float c0 = coeffs[0], c1 = coeffs[1];
#pragma unroll
    for (int tt = 0; tt < TL; ++tt) {
        float kn = ka[tt] * rn[tt];
        g_kphi[(b * LL + l0 + tt) * DD + e] = c0 * kn + c1 * kn * kn;
        float qv = tanhf(gain * qp[tt]);
        g_qphi[(b * LL + l0 + tt) * DD + e] = c0 * qv + c1 * qv * qv;
    }
}

// ---------------- postpass ----------------
__global__ __launch_bounds__(DD)
void postpass_kernel(const float* __restrict__ bout, float* __restrict__ out) {
    const int b = blockIdx.y, l0 = blockIdx.x * TL;
    const int e = threadIdx.x;
    __shared__ float ys[TL][DD];
#pragma unroll
    for (int tt = 0; tt < TL; ++tt) ys[tt][e] = g_y[(b * LL + l0 + tt) * DD + e];
    __syncthreads();
    float acc[TL];
#pragma unroll
    for (int tt = 0; tt < TL; ++tt) acc[tt] = 0.f;
    for (int d = 0; d < DD; ++d) {
        float w = g_WoT[d * DD + e];
#pragma unroll
        for (int tt = 0; tt < TL; ++tt) acc[tt] += ys[tt][d] * w;
    }
    const float bo = bout[e];
#pragma unroll
    for (int tt = 0; tt < TL; ++tt) out[(b * LL + l0 + tt) * DD + e] = acc[tt] + bo;
}

// ---------------- scan ----------------
// smem float offsets
#define OFF_S   0                          // 32*PP
#define OFF_Tm  4224                       // 32*PP
#define OFF_S0  8448                       // 128*PP (init only)
#define OFF_EB  25344                      // [2][128]
#define OFF_VB  25600
#define OFF_WP  25856                      // [2][4][128]
#define OFF_ZP  26880
#define OFF_WA  27904                      // [128]
#define OFF_ZA  28032
#define OFF_UA  28160                      // [32] u2 own rows
#define OFF_KB  28192                      // [2][128]
#define OFF_QS  28448
#define OFF_XN  28576                      // [2][128]
#define OFF_EN  28832                      // [32]
#define OFF_VNL 28864
#define OFF_SC  28896
#define OFF_SCR 28904                      // [256] init scratch
#define SCAN_FLOATS 29160
#define SCAN_SMEM (SCAN_FLOATS * 4)

#define UPD(X, idx) { \
    float Snv = A1 * S4.X + e_r * kc.X; \
    float Tnv = A2 * T4.X + alpha * ec.X + beta * vc.X; \
    float Unv = A3 * u[idx] + p_r * kc.X + cwv * wc.X + czv * zc.X; \
    u[idx] = Unv; \
    float mnv = 0.99f * m[idx] - cS * Snv + cU * Unv; \
    m[idx] = mnv; \
    accY += mnv * qc.X; accP += mnv * kn.X; accV += Snv * kn.X; \
    S4.X = Snv; T4.X = Tnv; }

__global__ __launch_bounds__(256, 1)
void scan_kernel(const float* __restrict__ x,
                 const float* __restrict__ M0,
                 const float* __restrict__ S0) {
    extern __shared__ float sm[];
    float* Ss   = sm + OFF_S;
    float* Ts   = sm + OFF_Tm;
    float* S0s  = sm + OFF_S0;
    float* eb   = sm + OFF_EB;
    float* vbuf = sm + OFF_VB;
    float* wa   = sm + OFF_WA;
    float* za   = sm + OFF_ZA;
    float* ua   = sm + OFF_UA;
    float* kb   = sm + OFF_KB;
    float* qs   = sm + OFF_QS;
    float* xn   = sm + OFF_XN;
    float* en   = sm + OFF_EN;
    float* vnl  = sm + OFF_VNL;
    float* sc   = sm + OFF_SC;
    float* scr  = sm + OFF_SCR;

    const uint32_t sbase = smem_u32(sm);
    const int tid = threadIdx.x;
    const int w = tid >> 5, lane = tid & 31;
    // Conflict-free mapping: within each 8-lane LDS.128 phase, granule index
    // (row*33 + 4*seg) mod 8 = (row + 4*seg) mod 8 takes all 8 values.
    const int lr = (w << 2) + (lane & 3);    // owned local row (0..31)
    const int sg = lane >> 2;                // 16-col segment (0..7)
    const int c0 = sg << 4;
    const uint32_t rk = cluster_rank();
    const int batch = blockIdx.x >> 2;
    const int rbase = (int)rk * RK;

    uint32_t pb[4];
#pragma unroll
    for (int i = 0; i < 4; ++i)
        asm("mapa.shared::cluster.u32 %0, %1, %2;" : "=r"(pb[i]) : "r"(sbase), "r"(i));

    const float* kphi = g_kphi + batch * LL * DD;
    const float* qphi = g_qphi + batch * LL * DD;
    const float* xb = x + batch * LL * DD;
    float* yb = g_y + batch * LL * DD;

    // ---------- init ----------
    for (int i = tid; i < DD * DD; i += 256) {
        int r = i >> 7, c = i & 127;
        S0s[r * PP + c] = S0[i];
    }
    if (tid < DD) {
        kb[tid] = kphi[tid];             // k_0
        kb[DD + tid] = kphi[DD + tid];   // k_1
        qs[tid] = qphi[tid];             // q_0
        xn[tid] = xb[DD + tid];          // x_1 (slot p=0)
    }
    float m[16], u[16];
#pragma unroll
    for (int j = 0; j < 16; ++j) m[j] = M0[(rbase + lr) * DD + c0 + j];
    __syncthreads();

    // sigma0
    {
        float ps = 0.f;
        for (int i = tid; i < DD * DD; i += 256) {
            int r = i >> 7, c = i & 127;
            float v = S0s[r * PP + c];
            ps += v * v;
        }
        scr[tid] = ps;
    }
    __syncthreads();
    if (tid < 32) {
        float s = 0.f;
#pragma unroll
        for (int j = 0; j < 8; ++j) s += scr[tid * 8 + j];
#pragma unroll
        for (int o = 16; o; o >>= 1) s += __shfl_xor_sync(0xffffffffu, s, o);
        if (tid == 0) sc[3] = s;
    }
    __syncthreads();
    float sig = sc[3];

    // S strip
    for (int i = tid; i < RK * DD; i += 256) {
        int r = i >> 7, c = i & 127;
        Ss[r * PP + c] = S0s[(rbase + r) * PP + c];
    }
    __syncthreads();
    // T strip + U regs
    if (sig != 0.0f) {
#pragma unroll 1
        for (int j = 0; j < 16; ++j) {
            int c = c0 + j;
            float a = 0.f;
            for (int k = 0; k < DD; ++k)
                a += S0s[(rbase + lr) * PP + k] * S0s[c * PP + k];
            Ts[lr * PP + c] = a;
        }
        __syncthreads();
#pragma unroll 1
        for (int j = 0; j < 16; ++j) {
            int c = c0 + j;
            float a = 0.f;
            for (int k = 0; k < DD; ++k)
                a += Ts[lr * PP + k] * S0s[k * PP + c];
            u[j] = a;
        }
    } else {
        for (int i = tid; i < RK * DD; i += 256) {
            int r = i >> 7, c = i & 127;
            Ts[r * PP + c] = 0.f;
        }
#pragma unroll
        for (int j = 0; j < 16; ++j) u[j] = 0.f;
    }
    __syncthreads();

    // e0 = M0 k0 - x0 ; v0 = S0 k0  (in-warp over 8-lane row groups, stride-4 lanes)
    {
        float pr = 0.f, vv = 0.f;
        const int base = lr * PP + c0;
#pragma unroll
        for (int j = 0; j < 16; ++j) {
            float kc = kb[c0 + j];
            pr += m[j] * kc;
            vv += Ss[base + j] * kc;
        }
#pragma unroll
        for (int o = 4; o <= 16; o <<= 1) {
            pr += __shfl_xor_sync(0xffffffffu, pr, o);
            vv += __shfl_xor_sync(0xffffffffu, vv, o);
        }
        if (sg == 0) {
            float e = pr - xb[rbase + lr];
            en[lr] = e; vnl[lr] = vv;
            uint32_t eo = (OFF_EB + rbase + lr) * 4;
            uint32_t vo = (OFF_VB + rbase + lr) * 4;
#pragma unroll
            for (int i = 0; i < 4; ++i) { pst(pb[i] + eo, e); pst(pb[i] + vo, vv); }
        }
    }
    __syncthreads();
    // w0/z0 column partials (1 thread per column per quantity)
    if (tid < 128) {
        int c = tid;
        float wv = 0.f;
#pragma unroll 8
        for (int r = 0; r < 32; ++r) wv += Ss[r * PP + c] * en[r];
        uint32_t wo = (OFF_WP + (int)rk * 128 + c) * 4;
#pragma unroll
        for (int i = 0; i < 4; ++i) pst(pb[i] + wo, wv);
    } else {
        int c = tid - 128;
        float zv = 0.f;
#pragma unroll 8
        for (int r = 0; r < 32; ++r) zv += Ss[r * PP + c] * vnl[r];
        uint32_t zo = (OFF_ZP + (int)rk * 128 + c) * 4;
#pragma unroll
        for (int i = 0; i < 4; ++i) pst(pb[i] + zo, zv);
    }
    CARRIVE();

    // ---------- main loop ----------
    for (int t = 0; t < LL; ++t) {
        const int p = t & 1;
        float rq = 0.f, rx = 0.f, rkk = 0.f;
        if (tid < 128) {   // prefetch; hides under CWAIT
            int t1 = (t + 1 < LL) ? t + 1 : LL - 1;
            int t2 = (t + 2 < LL) ? t + 2 : LL - 1;
            rq = qphi[t1 * DD + tid];
            rx = xb[t2 * DD + tid];
            rkk = kphi[t2 * DD + tid];
        }
        CWAIT();

        // phase 1a: assemble w/z from 4 CTA partials
        {
            int c = tid & 127;
            int srco = (tid < 128 ? OFF_WP : OFF_ZP) + p * 512 + c;
            float s = sm[srco] + sm[srco + 128] + sm[srco + 256] + sm[srco + 384];
            sm[(tid < 128 ? OFF_WA : OFF_ZA) + c] = s;
        }
        // phase 1b: u2[lr] = T_strip[lr,:] . e  (local row-dot; T symmetric)
        {
            const float* ecur = eb + p * DD;
            float s = 0.f;
            const int base = lr * PP + c0;
#pragma unroll
            for (int j4 = 0; j4 < 4; ++j4) {
                float4 t4 = *(const float4*)&Ts[base + j4 * 4];
                float4 e4 = *(const float4*)&ecur[c0 + j4 * 4];
                s += t4.x * e4.x + t4.y * e4.y + t4.z * e4.z + t4.w * e4.w;
            }
#pragma unroll
            for (int o = 4; o <= 16; o <<= 1) s += __shfl_xor_sync(0xffffffffu, s, o);
            if (sg == 0) ua[lr] = s;
        }
        // phase 1c: scalars kappa, eps, nu
        if (w < 3) {
            const float* va = (w == 0) ? (kb + p * DD) : (eb + p * DD);
            const float* vb2 = (w == 2) ? (vbuf + p * DD) : va;
            float s = 0.f;
#pragma unroll
            for (int i2 = 0; i2 < 4; ++i2) { int idx = lane + i2 * 32; s += va[idx] * vb2[idx]; }
#pragma unroll
            for (int o = 16; o; o >>= 1) s += __shfl_xor_sync(0xffffffffu, s, o);
            if (lane == 0) sc[w] = s;
        }
        __syncthreads();

        const float kappa = sc[0], eps = sc[1], nu = sc[2];
        sig = A2 * sig + 2.0f * A1 * nu + kappa * eps;
        const float nrm = sqrtf(sig) + 1e-6f;
        const float cS = 0.015f / nrm;
        const float cU = 0.005f / (nrm * nrm * nrm);

        // phase 2: fused strip update + in-warp matvecs + e/v production
        {
            const float e_r = eb[p * DD + rbase + lr];
            const float v_r = vbuf[p * DD + rbase + lr];
            const float u2r = ua[lr];
            const float alpha = A1 * v_r + kappa * e_r;
            const float beta = A1 * e_r;
            const float p_r = A2 * u2r + A1 * eps * v_r + (A1 * nu + kappa * eps) * e_r;
            const float cwv = A2 * v_r + A1 * kappa * e_r;
            const float czv = A2 * e_r;
            const float* kcur = kb + p * DD;
            const float* knxp = kb + (p ^ 1) * DD;
            const float* ecol = eb + p * DD;
            const float* vcol = vbuf + p * DD;
            float accY = 0.f, accP = 0.f, accV = 0.f;
            const int base = lr * PP + c0;
#pragma unroll
            for (int j4 = 0; j4 < 4; ++j4) {
                const int c = c0 + j4 * 4;
                float4 kc = *(const float4*)&kcur[c];
                float4 ec = *(const float4*)&ecol[c];
                float4 vc = *(const float4*)&vcol[c];
                float4 wc = *(const float4*)&wa[c];
                float4 zc = *(const float4*)&za[c];
                float4 qc = *(const float4*)&qs[c];
                float4 kn = *(const float4*)&knxp[c];
                float4 S4 = *(float4*)&Ss[base + j4 * 4];
                float4 T4 = *(float4*)&Ts[base + j4 * 4];
                UPD(x, j4 * 4 + 0)
                UPD(y, j4 * 4 + 1)
                UPD(z, j4 * 4 + 2)
                UPD(w, j4 * 4 + 3)
                *(float4*)&Ss[base + j4 * 4] = S4;
                *(float4*)&Ts[base + j4 * 4] = T4;
            }
#pragma unroll
            for (int o = 4; o <= 16; o <<= 1) {
                accY += __shfl_xor_sync(0xffffffffu, accY, o);
                accP += __shfl_xor_sync(0xffffffffu, accP, o);
                accV += __shfl_xor_sync(0xffffffffu, accV, o);
            }
            if (sg == 0) {
                float e = accP - xn[p * DD + rbase + lr];
                yb[t * DD + rbase + lr] = accY;
                en[lr] = e;
                vnl[lr] = accV;
                if (t + 1 < LL) {
                    uint32_t eo = (OFF_EB + (p ^ 1) * DD + rbase + lr) * 4;
                    uint32_t vo = (OFF_VB + (p ^ 1) * DD + rbase + lr) * 4;
#pragma unroll
                    for (int i = 0; i < 4; ++i) { pst(pb[i] + eo, e); pst(pb[i] + vo, accV); }
                }
            }
        }
        __syncthreads();

        // phase 4: w/z column partials + staging + exchange
        if (t + 1 < LL) {
            if (tid < 128) {
                int c = tid;
                float wv = 0.f;
#pragma unroll 8
                for (int r = 0; r < 32; ++r) wv += Ss[r * PP + c] * en[r];
                uint32_t wo = (OFF_WP + (p ^ 1) * 512 + (int)rk * 128 + c) * 4;
#pragma unroll
                for (int i = 0; i < 4; ++i) pst(pb[i] + wo, wv);
                qs[c] = rq;
                xn[(p ^ 1) * DD + c] = rx;
                kb[p * DD + c] = rkk;
            } else {
                int c = tid - 128;
                float zv = 0.f;
#pragma unroll 8
                for (int r = 0; r < 32; ++r) zv += Ss[r * PP + c] * vnl[r];
                uint32_t zo = (OFF_ZP + (p ^ 1) * 512 + (int)rk * 128 + c) * 4;
#pragma unroll
                for (int i = 0; i < 4; ++i) pst(pb[i] + zo, zv);
            }
            CARRIVE();
        }
    }
}

// ---------------- harness entry ----------------
extern "C" void kernel_launch(void* const* d_in, const int* in_sizes, int n_in,
                              void* d_out, int out_size) {
    const float* x    = (const float*)d_in[0];
    const float* Wq   = (const float*)d_in[1];
    const float* Wk   = (const float*)d_in[2];
    const float* P0   = (const float*)d_in[3];
    const float* M0   = (const float*)d_in[4];
    const float* S0   = (const float*)d_in[5];
    const float* lg   = (const float*)d_in[6];
    const float* cf   = (const float*)d_in[7];
    const float* Wout = (const float*)d_in[8];
    const float* bout = (const float*)d_in[9];
    float* out = (float*)d_out;

    cudaFuncSetAttribute(scan_kernel, cudaFuncAttributeMaxDynamicSharedMemorySize, SCAN_SMEM);

    transpose_k<<<dim3(4, 4, 3), dim3(32, 8)>>>(Wq, Wk, Wout);
    prepass_kernel<<<dim3(LL / TL, BB), DD>>>(x, P0, lg, cf);

    cudaLaunchConfig_t cfg = {};
    cfg.gridDim = dim3(CS * BB, 1, 1);
    cfg.blockDim = dim3(256, 1, 1);
    cfg.dynamicSmemBytes = SCAN_SMEM;
    cfg.stream = 0;
    cudaLaunchAttribute attrs[1];
    attrs[0].id = cudaLaunchAttributeClusterDimension;
    attrs[0].val.clusterDim.x = CS;
    attrs[0].val.clusterDim.y = 1;
    attrs[0].val.clusterDim.z = 1;
    cfg.attrs = attrs;
    cfg.numAttrs = 1;
    cudaLaunchKernelEx(&cfg, scan_kernel, x, M0, S0);

    postpass_kernel<<<dim3(LL / TL, BB), DD>>>(bout, out);
}

// round 15
// speedup vs baseline: 2.3510x; 1.1587x over previous
#include <cuda_runtime.h>
#include <math.h>
#include <stdint.h>

#define BB 16
#define LL 512
#define DD 128
#define EPSN 1e-12f
#define TL 16
#define CS 4
#define RK 32
#define PP 132

#define A1 0.9f
#define A2 0.81f
#define A3 0.729f

// Scratch (device globals; no allocation allowed)
__device__ float g_kphi[BB * LL * DD];
__device__ float g_qphi[BB * LL * DD];
__device__ float g_y[BB * LL * DD];
__device__ float g_WqT[DD * DD];
__device__ float g_WkT[DD * DD];
__device__ float g_WoT[DD * DD];

// ---------------- PTX helpers ----------------
__device__ __forceinline__ uint32_t smem_u32(const void* p) {
    uint32_t a;
    asm("{ .reg .u64 t; cvta.to.shared.u64 t, %1; cvt.u32.u64 %0, t; }" : "=r"(a) : "l"(p));
    return a;
}
__device__ __forceinline__ uint32_t cluster_rank() {
    uint32_t r;
    asm("mov.u32 %0, %%cluster_ctarank;" : "=r"(r));
    return r;
}
#define CARRIVE() asm volatile("barrier.cluster.arrive.aligned;" ::: "memory")
#define CWAIT()   asm volatile("barrier.cluster.wait.aligned;" ::: "memory")

__device__ __forceinline__ void pst(uint32_t addr, float v) {
    asm volatile("st.shared::cluster.b32 [%0], %1;" :: "r"(addr), "r"(__float_as_uint(v)) : "memory");
}

// ---------------- transpose Wq/Wk/Wout ----------------
__global__ void transpose_k(const float* __restrict__ Wq,
                            const float* __restrict__ Wk,
                            const float* __restrict__ Wo) {
    __shared__ float tb[32][33];
    const float* src = blockIdx.z == 0 ? Wq : (blockIdx.z == 1 ? Wk : Wo);
    float* dst = blockIdx.z == 0 ? g_WqT : (blockIdx.z == 1 ? g_WkT : g_WoT);
    int tx = threadIdx.x, ty = threadIdx.y;
    int bx = blockIdx.x * 32, by = blockIdx.y * 32;
#pragma unroll
    for (int j = 0; j < 32; j += 8) tb[ty + j][tx] = src[(by + ty + j) * DD + bx + tx];
    __syncthreads();
#pragma unroll
    for (int j = 0; j < 32; j += 8) dst[(bx + ty + j) * DD + by + tx] = tb[tx][ty + j];
}

// ---------------- prepass ----------------
__global__ __launch_bounds__(DD)
void prepass_kernel(const float* __restrict__ x,
                    const float* __restrict__ P0,
                    const float* __restrict__ log_gain,
                    const float* __restrict__ coeffs) {
    const int b = blockIdx.y, l0 = blockIdx.x * TL;
    const int e = threadIdx.x;
    __shared__ float xs[TL][DD];
    __shared__ float qs[TL][DD];
    __shared__ float rn[TL];

    const float* xp = x + (b * LL + l0) * DD;
#pragma unroll
    for (int tt = 0; tt < TL; ++tt) xs[tt][e] = xp[tt * DD + e];
    __syncthreads();

    float qa[TL], ka[TL];
#pragma unroll
    for (int tt = 0; tt < TL; ++tt) { qa[tt] = 0.f; ka[tt] = 0.f; }
    for (int d = 0; d < DD; ++d) {
        float wq = g_WqT[d * DD + e], wk = g_WkT[d * DD + e];
#pragma unroll
        for (int tt = 0; tt < TL; ++tt) {
            float xv = xs[tt][d];
            qa[tt] += xv * wq;
            ka[tt] += xv * wk;
        }
    }
#pragma unroll
    for (int tt = 0; tt < TL; ++tt) qs[tt][e] = qa[tt];
    __syncthreads();
#pragma unroll
    for (int tt = 0; tt < TL; ++tt) xs[tt][e] = ka[tt] * ka[tt];
    __syncthreads();
    {
        const int w = e >> 5, l = e & 31;
#pragma unroll
        for (int i = 0; i < 4; ++i) {
            int tt = w * 4 + i;
            float v = xs[tt][l] + xs[tt][l + 32] + xs[tt][l + 64] + xs[tt][l + 96];
#pragma unroll
            for (int o = 16; o; o >>= 1) v += __shfl_xor_sync(0xffffffffu, v, o);
            if (l == 0) rn[tt] = 1.0f / fmaxf(sqrtf(v), EPSN);
        }
    }
    __syncthreads();

    float qp[TL];
#pragma unroll
    for (int tt = 0; tt < TL; ++tt) qp[tt] = 0.f;
    for (int d = 0; d < DD; ++d) {
        float p = P0[d * DD + e];
#pragma unroll
        for (int tt = 0; tt < TL; ++tt) qp[tt] += qs[tt][d] * p;
    }
    const float gain = expf(log_gain[e]);
    const float c0 = coeffs[0], c1 = coeffs[1];
#pragma unroll
    for (int tt = 0; tt < TL; ++tt) {
        float kn = ka[tt] * rn[tt];
        g_kphi[(b * LL + l0 + tt) * DD + e] = c0 * kn + c1 * kn * kn;
        float qv = tanhf(gain * qp[tt]);
        g_qphi[(b * LL + l0 + tt) * DD + e] = c0 * qv + c1 * qv * qv;
    }
}

// ---------------- postpass ----------------
__global__ __launch_bounds__(DD)
void postpass_kernel(const float* __restrict__ bout, float* __restrict__ out) {
    const int b = blockIdx.y, l0 = blockIdx.x * TL;
    const int e = threadIdx.x;
    __shared__ float ys[TL][DD];
#pragma unroll
    for (int tt = 0; tt < TL; ++tt) ys[tt][e] = g_y[(b * LL + l0 + tt) * DD + e];
    __syncthreads();
    float acc[TL];
#pragma unroll
    for (int tt = 0; tt < TL; ++tt) acc[tt] = 0.f;
    for (int d = 0; d < DD; ++d) {
        float w = g_WoT[d * DD + e];
#pragma unroll
        for (int tt = 0; tt < TL; ++tt) acc[tt] += ys[tt][d] * w;
    }
    const float bo = bout[e];
#pragma unroll
    for (int tt = 0; tt < TL; ++tt) out[(b * LL + l0 + tt) * DD + e] = acc[tt] + bo;
}

// ---------------- scan: rank-structured recurrence, 4-CTA cluster ----------------
// smem float offsets (R10 layout)
#define OFF_S   0                          // 32*PP
#define OFF_Tm  (32*PP)                    // 32*PP
#define OFF_S0  (64*PP)                    // 128*PP (init only)
#define OFF_EB  (64*PP + 128*PP)           // [2][128]
#define OFF_VB  (OFF_EB + 256)
#define OFF_WP  (OFF_VB + 256)             // [2][4][128]
#define OFF_ZP  (OFF_WP + 1024)
#define OFF_UP  (OFF_ZP + 1024)
#define OFF_WA  (OFF_UP + 1024)            // [128]
#define OFF_ZA  (OFF_WA + 128)
#define OFF_UA  (OFF_ZA + 128)
#define OFF_KB  (OFF_UA + 128)             // [2][128]
#define OFF_QS  (OFF_KB + 256)
#define OFF_XN  (OFF_QS + 128)             // [2][128]
#define OFF_YP  (OFF_XN + 256)             // [32][9]
#define OFF_PR  (OFF_YP + 288)
#define OFF_VP  (OFF_PR + 288)
#define OFF_EN  (OFF_VP + 288)             // [32]
#define OFF_VNL (OFF_EN + 32)
#define OFF_SC  (OFF_VNL + 32)
#define SCAN_FLOATS (OFF_SC + 8)
#define SCAN_SMEM (SCAN_FLOATS * 4)

#define UPD(X, idx) { \
    float Snv = A1 * S4.X + e_r * kc.X; \
    float Tnv = A2 * T4.X + alpha * ec.X + beta * vc.X; \
    float Unv = A3 * u[idx] + p_r * kc.X + cwv * wc.X + czv * zc.X; \
    u[idx] = Unv; \
    float mnv = 0.99f * m[idx] - cS * Snv + cU * Unv; \
    m[idx] = mnv; \
    accY += mnv * qc.X; accP += mnv * kn.X; accV += Snv * kn.X; \
    S4.X = Snv; T4.X = Tnv; }

__global__ __launch_bounds__(256, 1)
void scan_kernel(const float* __restrict__ x,
                 const float* __restrict__ M0,
                 const float* __restrict__ S0) {
    extern __shared__ float sm[];
    float* Ss   = sm + OFF_S;
    float* Ts   = sm + OFF_Tm;
    float* S0s  = sm + OFF_S0;
    float* eb   = sm + OFF_EB;
    float* vbuf = sm + OFF_VB;
    float* wa   = sm + OFF_WA;
    float* za   = sm + OFF_ZA;
    float* ua   = sm + OFF_UA;
    float* kb   = sm + OFF_KB;
    float* qs   = sm + OFF_QS;
    float* xn   = sm + OFF_XN;
    float* yp   = sm + OFF_YP;
    float* prp  = sm + OFF_PR;
    float* vp   = sm + OFF_VP;
    float* en   = sm + OFF_EN;
    float* vnl  = sm + OFF_VNL;
    float* sc   = sm + OFF_SC;

    const uint32_t sbase = smem_u32(sm);
    const int tid = threadIdx.x;
    const int lane = tid & 31;           // owned local row
    const int cg = tid >> 5;             // 16-col group
    const int c0 = cg * 16;
    const uint32_t rk = cluster_rank();
    const int batch = blockIdx.x >> 2;
    const int rbase = (int)rk * RK;

    uint32_t pb[4];
#pragma unroll
    for (int i = 0; i < 4; ++i)
        asm("mapa.shared::cluster.u32 %0, %1, %2;" : "=r"(pb[i]) : "r"(sbase), "r"(i));

    const float* kphi = g_kphi + batch * LL * DD;
    const float* qphi = g_qphi + batch * LL * DD;
    const float* xb = x + batch * LL * DD;
    float* yb = g_y + batch * LL * DD;

    // ---------- init ----------
    for (int i = tid; i < DD * DD; i += 256) {
        int r = i >> 7, c = i & 127;
        S0s[r * PP + c] = S0[i];
    }
    if (tid < DD) {
        kb[tid] = kphi[tid];             // k_0
        kb[DD + tid] = kphi[DD + tid];   // k_1
        qs[tid] = qphi[tid];             // q_0
        xn[tid] = xb[DD + tid];          // x_1 (slot p=0)
    }
    float m[16], u[16];
#pragma unroll
    for (int j = 0; j < 16; ++j) m[j] = M0[(rbase + lane) * DD + c0 + j];
    __syncthreads();

    // sigma0 (deterministic fixed-order reduce)
    {
        float ps = 0.f;
        for (int i = tid; i < DD * DD; i += 256) {
            int r = i >> 7, c = i & 127;
            float v = S0s[r * PP + c];
            ps += v * v;
        }
        prp[tid] = ps;
    }
    __syncthreads();
    if (tid < 32) {
        float s = 0.f;
#pragma unroll
        for (int j = 0; j < 8; ++j) s += prp[tid * 8 + j];
#pragma unroll
        for (int o = 16; o; o >>= 1) s += __shfl_xor_sync(0xffffffffu, s, o);
        if (tid == 0) sc[3] = s;
    }
    __syncthreads();
    float sig = sc[3];

    // S strip
    for (int i = tid; i < RK * DD; i += 256) {
        int r = i >> 7, c = i & 127;
        Ss[r * PP + c] = S0s[(rbase + r) * PP + c];
    }
    __syncthreads();
    // T strip + U regs
    if (sig != 0.0f) {
#pragma unroll 1
        for (int j = 0; j < 16; ++j) {
            int c = c0 + j;
            float a = 0.f;
            for (int k = 0; k < DD; ++k)
                a += S0s[(rbase + lane) * PP + k] * S0s[c * PP + k];
            Ts[lane * PP + c] = a;
        }
        __syncthreads();
#pragma unroll 1
        for (int j = 0; j < 16; ++j) {
            int c = c0 + j;
            float a = 0.f;
            for (int k = 0; k < DD; ++k)
                a += Ts[lane * PP + k] * S0s[k * PP + c];
            u[j] = a;
        }
    } else {
        for (int i = tid; i < RK * DD; i += 256) {
            int r = i >> 7, c = i & 127;
            Ts[r * PP + c] = 0.f;
        }
#pragma unroll
        for (int j = 0; j < 16; ++j) u[j] = 0.f;
    }
    __syncthreads();

    // e0 = M0 k0 - x0 ; v0 = S0 k0 (strip partials, pitch-9 scratch)
    {
        float pr = 0.f, vv = 0.f;
        const int base = lane * PP + c0;
#pragma unroll
        for (int j = 0; j < 16; ++j) {
            float kc = kb[c0 + j];
            pr += m[j] * kc;
            vv += Ss[base + j] * kc;
        }
        prp[lane * 9 + cg] = pr;
        vp[lane * 9 + cg] = vv;
    }
    __syncthreads();
    if (tid < 32) {
        float s = 0.f;
#pragma unroll
        for (int j = 0; j < 8; ++j) s += prp[tid * 9 + j];
        float e = s - xb[rbase + tid];
        en[tid] = e;
        uint32_t eo = (OFF_EB + rbase + tid) * 4;
#pragma unroll
        for (int i = 0; i < 4; ++i) pst(pb[i] + eo, e);
    } else if (tid < 64) {
        int i2 = tid - 32;
        float s = 0.f;
#pragma unroll
        for (int j = 0; j < 8; ++j) s += vp[i2 * 9 + j];
        vnl[i2] = s;
        uint32_t vo = (OFF_VB + rbase + i2) * 4;
#pragma unroll
        for (int i = 0; i < 4; ++i) pst(pb[i] + vo, s);
    }
    __syncthreads();
    // w0/z0/u20 column partials — conflict-free (1 thread/col)
    if (tid < 128) {
        int c = tid;
        float wv = 0.f, zv = 0.f;
#pragma unroll 8
        for (int r = 0; r < 32; ++r) {
            float s = Ss[r * PP + c];
            wv += s * en[r];
            zv += s * vnl[r];
        }
        uint32_t wo = (OFF_WP + (int)rk * 128 + c) * 4;
        uint32_t zo = (OFF_ZP + (int)rk * 128 + c) * 4;
#pragma unroll
        for (int i = 0; i < 4; ++i) { pst(pb[i] + wo, wv); pst(pb[i] + zo, zv); }
    } else {
        int c = tid - 128;
        float uv = 0.f;
#pragma unroll 8
        for (int r = 0; r < 32; ++r) uv += Ts[r * PP + c] * en[r];
        uint32_t uo = (OFF_UP + (int)rk * 128 + c) * 4;
#pragma unroll
        for (int i = 0; i < 4; ++i) pst(pb[i] + uo, uv);
    }
    CARRIVE();

    // ---------- main loop ----------
    for (int t = 0; t < LL; ++t) {
        const int p = t & 1;
        float rq = 0.f, rx = 0.f, rkk = 0.f;
        if (tid < 128) {   // prefetch; latency hides under CWAIT
            int t1 = (t + 1 < LL) ? t + 1 : LL - 1;
            int t2 = (t + 2 < LL) ? t + 2 : LL - 1;
            rq = qphi[t1 * DD + tid];
            rx = xb[t2 * DD + tid];
            rkk = kphi[t2 * DD + tid];
        }
        CWAIT();

        // phase 1: assemble w/z/u2 + scalars
        for (int i = tid; i < 384; i += 256) {
            int c = i & 127, a_ = i >> 7;
            int srco = (a_ == 0 ? OFF_WP : (a_ == 1 ? OFF_ZP : OFF_UP)) + p * 512 + c;
            float s = sm[srco] + sm[srco + 128] + sm[srco + 256] + sm[srco + 384];
            sm[(a_ == 0 ? OFF_WA : (a_ == 1 ? OFF_ZA : OFF_UA)) + c] = s;
        }
        if (cg < 3) {
            const float* va = (cg == 0) ? (kb + p * DD) : (eb + p * DD);
            const float* vb2 = (cg == 2) ? (vbuf + p * DD) : va;
            float s = 0.f;
#pragma unroll
            for (int i2 = 0; i2 < 4; ++i2) { int idx = lane + i2 * 32; s += va[idx] * vb2[idx]; }
#pragma unroll
            for (int o = 16; o; o >>= 1) s += __shfl_xor_sync(0xffffffffu, s, o);
            if (lane == 0) sc[cg] = s;
        }
        __syncthreads();

        const float kappa = sc[0], eps = sc[1], nu = sc[2];
        sig = A2 * sig + 2.0f * A1 * nu + kappa * eps;
        const float nrm = sqrtf(sig) + 1e-6f;
        const float cS = 0.015f / nrm;
        const float cU = 0.005f / (nrm * nrm * nrm);

        // phase 2: fused strip update (float4, conflict-free pitch) + partials
        {
            const float e_r = eb[p * DD + rbase + lane];
            const float v_r = vbuf[p * DD + rbase + lane];
            const float u2r = ua[rbase + lane];
            const float alpha = A1 * v_r + kappa * e_r;
            const float beta = A1 * e_r;
            const float p_r = A2 * u2r + A1 * eps * v_r + (A1 * nu + kappa * eps) * e_r;
            const float cwv = A2 * v_r + A1 * kappa * e_r;
            const float czv = A2 * e_r;
            const float* kcur = kb + p * DD;
            const float* knxp = kb + (p ^ 1) * DD;
            const float* ecol = eb + p * DD;
            const float* vcol = vbuf + p * DD;
            float accY = 0.f, accP = 0.f, accV = 0.f;
            const int base = lane * PP + c0;
#pragma unroll
            for (int j4 = 0; j4 < 4; ++j4) {
                const int c = c0 + j4 * 4;
                float4 kc = *(const float4*)&kcur[c];
                float4 ec = *(const float4*)&ecol[c];
                float4 vc = *(const float4*)&vcol[c];
                float4 wc = *(const float4*)&wa[c];
                float4 zc = *(const float4*)&za[c];
                float4 qc = *(const float4*)&qs[c];
                float4 kn = *(const float4*)&knxp[c];
                float4 S4 = *(float4*)&Ss[base + j4 * 4];
                float4 T4 = *(float4*)&Ts[base + j4 * 4];
                UPD(x, j4 * 4 + 0)
                UPD(y, j4 * 4 + 1)
                UPD(z, j4 * 4 + 2)
                UPD(w, j4 * 4 + 3)
                *(float4*)&Ss[base + j4 * 4] = S4;
                *(float4*)&Ts[base + j4 * 4] = T4;
            }
            yp[lane * 9 + cg] = accY;
            prp[lane * 9 + cg] = accP;
            vp[lane * 9 + cg] = accV;
        }
        __syncthreads();

        // phase 3: reductions + peer exchange of e,v
        if (tid < 32) {
            float s = 0.f;
#pragma unroll
            for (int j = 0; j < 8; ++j) s += yp[tid * 9 + j];
            yb[t * DD + rbase + tid] = s;
        } else if (tid < 64) {
            int i2 = tid - 32;
            float s = 0.f;
#pragma unroll
            for (int j = 0; j < 8; ++j) s += prp[i2 * 9 + j];
            float e = s - xn[p * DD + rbase + i2];
            en[i2] = e;
            if (t + 1 < LL) {
                uint32_t eo = (OFF_EB + (p ^ 1) * DD + rbase + i2) * 4;
#pragma unroll
                for (int i = 0; i < 4; ++i) pst(pb[i] + eo, e);
            }
        } else if (tid < 96) {
            int i2 = tid - 64;
            float s = 0.f;
#pragma unroll
            for (int j = 0; j < 8; ++j) s += vp[i2 * 9 + j];
            vnl[i2] = s;
            if (t + 1 < LL) {
                uint32_t vo = (OFF_VB + (p ^ 1) * DD + rbase + i2) * 4;
#pragma unroll
                for (int i = 0; i < 4; ++i) pst(pb[i] + vo, s);
            }
        }
        __syncthreads();

        // phase 4: conflict-free column partials + staging + exchange
        if (t + 1 < LL) {
            if (tid < 128) {
                int c = tid;
                float wv = 0.f, zv = 0.f;
#pragma unroll 8
                for (int r = 0; r < 32; ++r) {
                    float s = Ss[r * PP + c];
                    wv += s * en[r];
                    zv += s * vnl[r];
                }
                uint32_t wo = (OFF_WP + (p ^ 1) * 512 + (int)rk * 128 + c) * 4;
                uint32_t zo = (OFF_ZP + (p ^ 1) * 512 + (int)rk * 128 + c) * 4;
#pragma unroll
                for (int i = 0; i < 4; ++i) { pst(pb[i] + wo, wv); pst(pb[i] + zo, zv); }
                qs[c] = rq;
                xn[(p ^ 1) * DD + c] = rx;
                kb[p * DD + c] = rkk;
            } else {
                int c = tid - 128;
                float uv = 0.f;
#pragma unroll 8
                for (int r = 0; r < 32; ++r) uv += Ts[r * PP + c] * en[r];
                uint32_t uo = (OFF_UP + (p ^ 1) * 512 + (int)rk * 128 + c) * 4;
#pragma unroll
                for (int i = 0; i < 4; ++i) pst(pb[i] + uo, uv);
            }
            CARRIVE();
        }
    }
}

// ---------------- harness entry ----------------
extern "C" void kernel_launch(void* const* d_in, const int* in_sizes, int n_in,
                              void* d_out, int out_size) {
    const float* x    = (const float*)d_in[0];
    const float* Wq   = (const float*)d_in[1];
    const float* Wk   = (const float*)d_in[2];
    const float* P0   = (const float*)d_in[3];
    const float* M0   = (const float*)d_in[4];
    const float* S0   = (const float*)d_in[5];
    const float* lg   = (const float*)d_in[6];
    const float* cf   = (const float*)d_in[7];
    const float* Wout = (const float*)d_in[8];
    const float* bout = (const float*)d_in[9];
    float* out = (float*)d_out;

    cudaFuncSetAttribute(scan_kernel, cudaFuncAttributeMaxDynamicSharedMemorySize, SCAN_SMEM);

    transpose_k<<<dim3(4, 4, 3), dim3(32, 8)>>>(Wq, Wk, Wout);
    prepass_kernel<<<dim3(LL / TL, BB), DD>>>(x, P0, lg, cf);

    cudaLaunchConfig_t cfg = {};
    cfg.gridDim = dim3(CS * BB, 1, 1);
    cfg.blockDim = dim3(256, 1, 1);
    cfg.dynamicSmemBytes = SCAN_SMEM;
    cfg.stream = 0;
    cudaLaunchAttribute attrs[1];
    attrs[0].id = cudaLaunchAttributeClusterDimension;
    attrs[0].val.clusterDim.x = CS;
    attrs[0].val.clusterDim.y = 1;
    attrs[0].val.clusterDim.z = 1;
    cfg.attrs = attrs;
    cfg.numAttrs = 1;
    cudaLaunchKernelEx(&cfg, scan_kernel, x, M0, S0);

    postpass_kernel<<<dim3(LL / TL, BB), DD>>>(bout, out);
}

// round 16
// speedup vs baseline: 2.5781x; 1.0966x over previous
#include <cuda_runtime.h>
#include <math.h>
#include <stdint.h>

#define BB 16
#define LL 512
#define DD 128
#define EPSN 1e-12f
#define TL 16
#define CS 4
#define RK 32
#define PP 132

#define A1 0.9f
#define A2 0.81f
#define A3 0.729f

// Scratch (device globals; no allocation allowed)
__device__ float g_kphi[BB * LL * DD];
__device__ float g_qphi[BB * LL * DD];
__device__ float g_y[BB * LL * DD];
__device__ float g_WqT[DD * DD];
__device__ float g_WkT[DD * DD];
__device__ float g_WoT[DD * DD];

// ---------------- PTX helpers ----------------
__device__ __forceinline__ uint32_t smem_u32(const void* p) {
    uint32_t a;
    asm("{ .reg .u64 t; cvta.to.shared.u64 t, %1; cvt.u32.u64 %0, t; }" : "=r"(a) : "l"(p));
    return a;
}
__device__ __forceinline__ uint32_t cluster_rank() {
    uint32_t r;
    asm("mov.u32 %0, %%cluster_ctarank;" : "=r"(r));
    return r;
}
#define CARRIVE() asm volatile("barrier.cluster.arrive.aligned;" ::: "memory")
#define CWAIT()   asm volatile("barrier.cluster.wait.aligned;" ::: "memory")

__device__ __forceinline__ void pst(uint32_t addr, float v) {
    asm volatile("st.shared::cluster.b32 [%0], %1;" :: "r"(addr), "r"(__float_as_uint(v)) : "memory");
}

// ---------------- transpose Wq/Wk/Wout ----------------
__global__ void transpose_k(const float* __restrict__ Wq,
                            const float* __restrict__ Wk,
                            const float* __restrict__ Wo) {
    __shared__ float tb[32][33];
    const float* src = blockIdx.z == 0 ? Wq : (blockIdx.z == 1 ? Wk : Wo);
    float* dst = blockIdx.z == 0 ? g_WqT : (blockIdx.z == 1 ? g_WkT : g_WoT);
    int tx = threadIdx.x, ty = threadIdx.y;
    int bx = blockIdx.x * 32, by = blockIdx.y * 32;
#pragma unroll
    for (int j = 0; j < 32; j += 8) tb[ty + j][tx] = src[(by + ty + j) * DD + bx + tx];
    __syncthreads();
#pragma unroll
    for (int j = 0; j < 32; j += 8) dst[(bx + ty + j) * DD + by + tx] = tb[tx][ty + j];
}

// ---------------- prepass ----------------
__global__ __launch_bounds__(DD)
void prepass_kernel(const float* __restrict__ x,
                    const float* __restrict__ P0,
                    const float* __restrict__ log_gain,
                    const float* __restrict__ coeffs) {
    const int b = blockIdx.y, l0 = blockIdx.x * TL;
    const int e = threadIdx.x;
    __shared__ float xs[TL][DD];
    __shared__ float qs[TL][DD];
    __shared__ float rn[TL];

    const float* xp = x + (b * LL + l0) * DD;
#pragma unroll
    for (int tt = 0; tt < TL; ++tt) xs[tt][e] = xp[tt * DD + e];
    __syncthreads();

    float qa[TL], ka[TL];
#pragma unroll
    for (int tt = 0; tt < TL; ++tt) { qa[tt] = 0.f; ka[tt] = 0.f; }
    for (int d = 0; d < DD; ++d) {
        float wq = g_WqT[d * DD + e], wk = g_WkT[d * DD + e];
#pragma unroll
        for (int tt = 0; tt < TL; ++tt) {
            float xv = xs[tt][d];
            qa[tt] += xv * wq;
            ka[tt] += xv * wk;
        }
    }
#pragma unroll
    for (int tt = 0; tt < TL; ++tt) qs[tt][e] = qa[tt];
    __syncthreads();
#pragma unroll
    for (int tt = 0; tt < TL; ++tt) xs[tt][e] = ka[tt] * ka[tt];
    __syncthreads();
    {
        const int w = e >> 5, l = e & 31;
#pragma unroll
        for (int i = 0; i < 4; ++i) {
            int tt = w * 4 + i;
            float v = xs[tt][l] + xs[tt][l + 32] + xs[tt][l + 64] + xs[tt][l + 96];
#pragma unroll
            for (int o = 16; o; o >>= 1) v += __shfl_xor_sync(0xffffffffu, v, o);
            if (l == 0) rn[tt] = 1.0f / fmaxf(sqrtf(v), EPSN);
        }
    }
    __syncthreads();

    float qp[TL];
#pragma unroll
    for (int tt = 0; tt < TL; ++tt) qp[tt] = 0.f;
    for (int d = 0; d < DD; ++d) {
        float p = P0[d * DD + e];
#pragma unroll
        for (int tt = 0; tt < TL; ++tt) qp[tt] += qs[tt][d] * p;
    }
    const float gain = expf(log_gain[e]);
    const float c0 = coeffs[0], c1 = coeffs[1];
#pragma unroll
    for (int tt = 0; tt < TL; ++tt) {
        float kn = ka[tt] * rn[tt];
        g_kphi[(b * LL + l0 + tt) * DD + e] = c0 * kn + c1 * kn * kn;
        float qv = tanhf(gain * qp[tt]);
        g_qphi[(b * LL + l0 + tt) * DD + e] = c0 * qv + c1 * qv * qv;
    }
}

// ---------------- postpass ----------------
__global__ __launch_bounds__(DD)
void postpass_kernel(const float* __restrict__ bout, float* __restrict__ out) {
    const int b = blockIdx.y, l0 = blockIdx.x * TL;
    const int e = threadIdx.x;
    __shared__ float ys[TL][DD];
#pragma unroll
    for (int tt = 0; tt < TL; ++tt) ys[tt][e] = g_y[(b * LL + l0 + tt) * DD + e];
    __syncthreads();
    float acc[TL];
#pragma unroll
    for (int tt = 0; tt < TL; ++tt) acc[tt] = 0.f;
    for (int d = 0; d < DD; ++d) {
        float w = g_WoT[d * DD + e];
#pragma unroll
        for (int tt = 0; tt < TL; ++tt) acc[tt] += ys[tt][d] * w;
    }
    const float bo = bout[e];
#pragma unroll
    for (int tt = 0; tt < TL; ++tt) out[(b * LL + l0 + tt) * DD + e] = acc[tt] + bo;
}

// ---------------- scan: rank-structured recurrence, 4-CTA cluster ----------------
// smem float offsets
#define OFF_S   0                          // 32*PP
#define OFF_Tm  (32*PP)                    // 32*PP
#define OFF_S0  (64*PP)                    // 128*PP (init only)
#define OFF_EB  (64*PP + 128*PP)           // [2][128]
#define OFF_VB  (OFF_EB + 256)
#define OFF_WP  (OFF_VB + 256)             // [2][4][128]
#define OFF_ZP  (OFF_WP + 1024)
#define OFF_WA  (OFF_ZP + 1024)            // [128]
#define OFF_ZA  (OFF_WA + 128)
#define OFF_UP2 (OFF_ZA + 128)             // [32][9] u2 partials (local, T-symmetric)
#define OFF_KB  (OFF_UP2 + 288)            // [2][128]
#define OFF_QS  (OFF_KB + 256)
#define OFF_XN  (OFF_QS + 128)             // [2][128]
#define OFF_YP  (OFF_XN + 256)             // [32][9]
#define OFF_PR  (OFF_YP + 288)
#define OFF_VP  (OFF_PR + 288)
#define OFF_EN  (OFF_VP + 288)             // [32]
#define OFF_VNL (OFF_EN + 32)
#define OFF_SC  (OFF_VNL + 32)
#define SCAN_FLOATS (OFF_SC + 8)
#define SCAN_SMEM (SCAN_FLOATS * 4)

#define UPD(X, idx) { \
    float Snv = A1 * S4.X + e_r * kc.X; \
    float Tnv = A2 * T4.X + alpha * ec.X + beta * vc.X; \
    float Unv = A3 * u[idx] + p_r * kc.X + cwv * wc.X + czv * zc.X; \
    u[idx] = Unv; \
    float mnv = 0.99f * m[idx] - cS * Snv + cU * Unv; \
    m[idx] = mnv; \
    accY += mnv * qc.X; accP += mnv * kn.X; accV += Snv * kn.X; \
    S4.X = Snv; T4.X = Tnv; }

__global__ __launch_bounds__(256, 1)
void scan_kernel(const float* __restrict__ x,
                 const float* __restrict__ M0,
                 const float* __restrict__ S0) {
    extern __shared__ float sm[];
    float* Ss   = sm + OFF_S;
    float* Ts   = sm + OFF_Tm;
    float* S0s  = sm + OFF_S0;
    float* eb   = sm + OFF_EB;
    float* vbuf = sm + OFF_VB;
    float* wa   = sm + OFF_WA;
    float* za   = sm + OFF_ZA;
    float* up2  = sm + OFF_UP2;
    float* kb   = sm + OFF_KB;
    float* qs   = sm + OFF_QS;
    float* xn   = sm + OFF_XN;
    float* yp   = sm + OFF_YP;
    float* prp  = sm + OFF_PR;
    float* vp   = sm + OFF_VP;
    float* en   = sm + OFF_EN;
    float* vnl  = sm + OFF_VNL;
    float* sc   = sm + OFF_SC;

    const uint32_t sbase = smem_u32(sm);
    const int tid = threadIdx.x;
    const int lane = tid & 31;           // owned local row
    const int cg = tid >> 5;             // 16-col group
    const int c0 = cg * 16;
    const uint32_t rk = cluster_rank();
    const int batch = blockIdx.x >> 2;
    const int rbase = (int)rk * RK;

    uint32_t pb[4];
#pragma unroll
    for (int i = 0; i < 4; ++i)
        asm("mapa.shared::cluster.u32 %0, %1, %2;" : "=r"(pb[i]) : "r"(sbase), "r"(i));

    const float* kphi = g_kphi + batch * LL * DD;
    const float* qphi = g_qphi + batch * LL * DD;
    const float* xb = x + batch * LL * DD;
    float* yb = g_y + batch * LL * DD;

    // ---------- init ----------
    for (int i = tid; i < DD * DD; i += 256) {
        int r = i >> 7, c = i & 127;
        S0s[r * PP + c] = S0[i];
    }
    if (tid < DD) {
        kb[tid] = kphi[tid];             // k_0
        kb[DD + tid] = kphi[DD + tid];   // k_1
        qs[tid] = qphi[tid];             // q_0
        xn[tid] = xb[DD + tid];          // x_1 (slot p=0)
    }
    float m[16], u[16];
#pragma unroll
    for (int j = 0; j < 16; ++j) m[j] = M0[(rbase + lane) * DD + c0 + j];
    __syncthreads();

    // sigma0 (deterministic fixed-order reduce)
    {
        float ps = 0.f;
        for (int i = tid; i < DD * DD; i += 256) {
            int r = i >> 7, c = i & 127;
            float v = S0s[r * PP + c];
            ps += v * v;
        }
        prp[tid] = ps;
    }
    __syncthreads();
    if (tid < 32) {
        float s = 0.f;
#pragma unroll
        for (int j = 0; j < 8; ++j) s += prp[tid * 8 + j];
#pragma unroll
        for (int o = 16; o; o >>= 1) s += __shfl_xor_sync(0xffffffffu, s, o);
        if (tid == 0) sc[3] = s;
    }
    __syncthreads();
    float sig = sc[3];

    // S strip
    for (int i = tid; i < RK * DD; i += 256) {
        int r = i >> 7, c = i & 127;
        Ss[r * PP + c] = S0s[(rbase + r) * PP + c];
    }
    __syncthreads();
    // T strip + U regs
    if (sig != 0.0f) {
#pragma unroll 1
        for (int j = 0; j < 16; ++j) {
            int c = c0 + j;
            float a = 0.f;
            for (int k = 0; k < DD; ++k)
                a += S0s[(rbase + lane) * PP + k] * S0s[c * PP + k];
            Ts[lane * PP + c] = a;
        }
        __syncthreads();
#pragma unroll 1
        for (int j = 0; j < 16; ++j) {
            int c = c0 + j;
            float a = 0.f;
            for (int k = 0; k < DD; ++k)
                a += Ts[lane * PP + k] * S0s[k * PP + c];
            u[j] = a;
        }
    } else {
        for (int i = tid; i < RK * DD; i += 256) {
            int r = i >> 7, c = i & 127;
            Ts[r * PP + c] = 0.f;
        }
#pragma unroll
        for (int j = 0; j < 16; ++j) u[j] = 0.f;
    }
    __syncthreads();

    // e0 = M0 k0 - x0 ; v0 = S0 k0 (strip partials, pitch-9 scratch)
    {
        float pr = 0.f, vv = 0.f;
        const int base = lane * PP + c0;
#pragma unroll
        for (int j = 0; j < 16; ++j) {
            float kc = kb[c0 + j];
            pr += m[j] * kc;
            vv += Ss[base + j] * kc;
        }
        prp[lane * 9 + cg] = pr;
        vp[lane * 9 + cg] = vv;
    }
    __syncthreads();
    if (tid < 32) {
        float s = 0.f;
#pragma unroll
        for (int j = 0; j < 8; ++j) s += prp[tid * 9 + j];
        float e = s - xb[rbase + tid];
        en[tid] = e;
        uint32_t eo = (OFF_EB + rbase + tid) * 4;
#pragma unroll
        for (int i = 0; i < 4; ++i) pst(pb[i] + eo, e);
    } else if (tid < 64) {
        int i2 = tid - 32;
        float s = 0.f;
#pragma unroll
        for (int j = 0; j < 8; ++j) s += vp[i2 * 9 + j];
        vnl[i2] = s;
        uint32_t vo = (OFF_VB + rbase + i2) * 4;
#pragma unroll
        for (int i = 0; i < 4; ++i) pst(pb[i] + vo, s);
    }
    __syncthreads();
    // w0/z0 column partials — conflict-free (1 thread/col); u2 is local now
    if (tid < 128) {
        int c = tid;
        float wv = 0.f, zv = 0.f;
#pragma unroll 8
        for (int r = 0; r < 32; ++r) {
            float s = Ss[r * PP + c];
            wv += s * en[r];
            zv += s * vnl[r];
        }
        uint32_t wo = (OFF_WP + (int)rk * 128 + c) * 4;
        uint32_t zo = (OFF_ZP + (int)rk * 128 + c) * 4;
#pragma unroll
        for (int i = 0; i < 4; ++i) { pst(pb[i] + wo, wv); pst(pb[i] + zo, zv); }
    }
    CARRIVE();

    // ---------- main loop ----------
    for (int t = 0; t < LL; ++t) {
        const int p = t & 1;
        float rq = 0.f, rx = 0.f, rkk = 0.f;
        if (tid >= 128) {   // prefetch (upper half); latency hides under CWAIT
            int i2 = tid - 128;
            int t1 = (t + 1 < LL) ? t + 1 : LL - 1;
            int t2 = (t + 2 < LL) ? t + 2 : LL - 1;
            rq = qphi[t1 * DD + i2];
            rx = xb[t2 * DD + i2];
            rkk = kphi[t2 * DD + i2];
        }
        CWAIT();

        // phase 1a: assemble w/z from 4 CTA partials (one item/thread)
        {
            int c = tid & 127;
            int srco = (tid < 128 ? OFF_WP : OFF_ZP) + p * 512 + c;
            float s = sm[srco] + sm[srco + 128] + sm[srco + 256] + sm[srco + 384];
            sm[(tid < 128 ? OFF_WA : OFF_ZA) + c] = s;
        }
        // phase 1b: u2 partials from local T strip (T symmetric: u2 = T e)
        {
            const float* ecur = eb + p * DD;
            float s = 0.f;
            const int base = lane * PP + c0;
#pragma unroll
            for (int j4 = 0; j4 < 4; ++j4) {
                float4 t4 = *(const float4*)&Ts[base + j4 * 4];
                float4 e4 = *(const float4*)&ecur[c0 + j4 * 4];
                s += t4.x * e4.x + t4.y * e4.y + t4.z * e4.z + t4.w * e4.w;
            }
            up2[lane * 9 + cg] = s;
        }
        // phase 1c: scalars kappa, eps, nu
        if (cg < 3) {
            const float* va = (cg == 0) ? (kb + p * DD) : (eb + p * DD);
            const float* vb2 = (cg == 2) ? (vbuf + p * DD) : va;
            float s = 0.f;
#pragma unroll
            for (int i2 = 0; i2 < 4; ++i2) { int idx = lane + i2 * 32; s += va[idx] * vb2[idx]; }
#pragma unroll
            for (int o = 16; o; o >>= 1) s += __shfl_xor_sync(0xffffffffu, s, o);
            if (lane == 0) sc[cg] = s;
        }
        __syncthreads();

        const float kappa = sc[0], eps = sc[1], nu = sc[2];
        sig = A2 * sig + 2.0f * A1 * nu + kappa * eps;
        const float nrm = sqrtf(sig) + 1e-6f;
        const float cS = 0.015f / nrm;
        const float cU = 0.005f / (nrm * nrm * nrm);

        // phase 2: fused strip update (float4, conflict-free pitch) + partials
        {
            const float e_r = eb[p * DD + rbase + lane];
            const float v_r = vbuf[p * DD + rbase + lane];
            float u2r = up2[lane * 9 + 0] + up2[lane * 9 + 1] + up2[lane * 9 + 2] + up2[lane * 9 + 3]
                      + up2[lane * 9 + 4] + up2[lane * 9 + 5] + up2[lane * 9 + 6] + up2[lane * 9 + 7];
            const float alpha = A1 * v_r + kappa * e_r;
            const float beta = A1 * e_r;
            const float p_r = A2 * u2r + A1 * eps * v_r + (A1 * nu + kappa * eps) * e_r;
            const float cwv = A2 * v_r + A1 * kappa * e_r;
            const float czv = A2 * e_r;
            const float* kcur = kb + p * DD;
            const float* knxp = kb + (p ^ 1) * DD;
            const float* ecol = eb + p * DD;
            const float* vcol = vbuf + p * DD;
            float accY = 0.f, accP = 0.f, accV = 0.f;
            const int base = lane * PP + c0;
#pragma unroll
            for (int j4 = 0; j4 < 4; ++j4) {
                const int c = c0 + j4 * 4;
                float4 kc = *(const float4*)&kcur[c];
                float4 ec = *(const float4*)&ecol[c];
                float4 vc = *(const float4*)&vcol[c];
                float4 wc = *(const float4*)&wa[c];
                float4 zc = *(const float4*)&za[c];
                float4 qc = *(const float4*)&qs[c];
                float4 kn = *(const float4*)&knxp[c];
                float4 S4 = *(float4*)&Ss[base + j4 * 4];
                float4 T4 = *(float4*)&Ts[base + j4 * 4];
                UPD(x, j4 * 4 + 0)
                UPD(y, j4 * 4 + 1)
                UPD(z, j4 * 4 + 2)
                UPD(w, j4 * 4 + 3)
                *(float4*)&Ss[base + j4 * 4] = S4;
                *(float4*)&Ts[base + j4 * 4] = T4;
            }
            yp[lane * 9 + cg] = accY;
            prp[lane * 9 + cg] = accP;
            vp[lane * 9 + cg] = accV;
        }
        __syncthreads();

        // phase 3: reductions + peer exchange of e,v
        if (tid < 32) {
            float s = 0.f;
#pragma unroll
            for (int j = 0; j < 8; ++j) s += yp[tid * 9 + j];
            yb[t * DD + rbase + tid] = s;
        } else if (tid < 64) {
            int i2 = tid - 32;
            float s = 0.f;
#pragma unroll
            for (int j = 0; j < 8; ++j) s += prp[i2 * 9 + j];
            float e = s - xn[p * DD + rbase + i2];
            en[i2] = e;
            if (t + 1 < LL) {
                uint32_t eo = (OFF_EB + (p ^ 1) * DD + rbase + i2) * 4;
#pragma unroll
                for (int i = 0; i < 4; ++i) pst(pb[i] + eo, e);
            }
        } else if (tid < 96) {
            int i2 = tid - 64;
            float s = 0.f;
#pragma unroll
            for (int j = 0; j < 8; ++j) s += vp[i2 * 9 + j];
            vnl[i2] = s;
            if (t + 1 < LL) {
                uint32_t vo = (OFF_VB + (p ^ 1) * DD + rbase + i2) * 4;
#pragma unroll
                for (int i = 0; i < 4; ++i) pst(pb[i] + vo, s);
            }
        }
        __syncthreads();

        // phase 4: conflict-free w/z column partials + staging + exchange
        if (t + 1 < LL) {
            if (tid < 128) {
                int c = tid;
                float wv = 0.f, zv = 0.f;
#pragma unroll 8
                for (int r = 0; r < 32; ++r) {
                    float s = Ss[r * PP + c];
                    wv += s * en[r];
                    zv += s * vnl[r];
                }
                uint32_t wo = (OFF_WP + (p ^ 1) * 512 + (int)rk * 128 + c) * 4;
                uint32_t zo = (OFF_ZP + (p ^ 1) * 512 + (int)rk * 128 + c) * 4;
#pragma unroll
                for (int i = 0; i < 4; ++i) { pst(pb[i] + wo, wv); pst(pb[i] + zo, zv); }
            } else {
                int c = tid - 128;
                qs[c] = rq;
                xn[(p ^ 1) * DD + c] = rx;
                kb[p * DD + c] = rkk;
            }
            CARRIVE();
        }
    }
}

// ---------------- harness entry ----------------
extern "C" void kernel_launch(void* const* d_in, const int* in_sizes, int n_in,
                              void* d_out, int out_size) {
    const float* x    = (const float*)d_in[0];
    const float* Wq   = (const float*)d_in[1];
    const float* Wk   = (const float*)d_in[2];
    const float* P0   = (const float*)d_in[3];
    const float* M0   = (const float*)d_in[4];
    const float* S0   = (const float*)d_in[5];
    const float* lg   = (const float*)d_in[6];
    const float* cf   = (const float*)d_in[7];
    const float* Wout = (const float*)d_in[8];
    const float* bout = (const float*)d_in[9];
    float* out = (float*)d_out;

    cudaFuncSetAttribute(scan_kernel, cudaFuncAttributeMaxDynamicSharedMemorySize, SCAN_SMEM);

    transpose_k<<<dim3(4, 4, 3), dim3(32, 8)>>>(Wq, Wk, Wout);
    prepass_kernel<<<dim3(LL / TL, BB), DD>>>(x, P0, lg, cf);

    cudaLaunchConfig_t cfg = {};
    cfg.gridDim = dim3(CS * BB, 1, 1);
    cfg.blockDim = dim3(256, 1, 1);
    cfg.dynamicSmemBytes = SCAN_SMEM;
    cfg.stream = 0;
    cudaLaunchAttribute attrs[1];
    attrs[0].id = cudaLaunchAttributeClusterDimension;
    attrs[0].val.clusterDim.x = CS;
    attrs[0].val.clusterDim.y = 1;
    attrs[0].val.clusterDim.z = 1;
    cfg.attrs = attrs;
    cfg.numAttrs = 1;
    cudaLaunchKernelEx(&cfg, scan_kernel, x, M0, S0);

    postpass_kernel<<<dim3(LL / TL, BB), DD>>>(bout, out);
}

// round 17
// speedup vs baseline: 2.7234x; 1.0564x over previous
#include <cuda_runtime.h>
#include <math.h>
#include <stdint.h>

#define BB 16
#define LL 512
#define DD 128
#define EPSN 1e-12f
#define TL 16
#define CS 4
#define RK 32
#define PP 132

#define A1 0.9f
#define A2 0.81f
#define A3 0.729f

typedef unsigned long long u64c;

// Scratch (device globals; no allocation allowed)
__device__ float g_kphi[BB * LL * DD];
__device__ float g_qphi[BB * LL * DD];
__device__ float g_y[BB * LL * DD];
__device__ float g_WqT[DD * DD];
__device__ float g_WkT[DD * DD];
__device__ float g_WoT[DD * DD];

// ---------------- PTX helpers ----------------
__device__ __forceinline__ uint32_t smem_u32(const void* p) {
    uint32_t a;
    asm("{ .reg .u64 t; cvta.to.shared.u64 t, %1; cvt.u32.u64 %0, t; }" : "=r"(a) : "l"(p));
    return a;
}
__device__ __forceinline__ uint32_t cluster_rank() {
    uint32_t r;
    asm("mov.u32 %0, %%cluster_ctarank;" : "=r"(r));
    return r;
}
#define CARRIVE() asm volatile("barrier.cluster.arrive.aligned;" ::: "memory")
#define CWAIT()   asm volatile("barrier.cluster.wait.aligned;" ::: "memory")

__device__ __forceinline__ void pst(uint32_t addr, float v) {
    asm volatile("st.shared::cluster.b32 [%0], %1;" :: "r"(addr), "r"(__float_as_uint(v)) : "memory");
}

// ---- packed f32x2 ----
__device__ __forceinline__ u64c pk2(float lo, float hi) {
    u64c r; asm("mov.b64 %0, {%1, %2};" : "=l"(r) : "f"(lo), "f"(hi)); return r;
}
__device__ __forceinline__ u64c fma2(u64c a, u64c b, u64c c) {
    u64c d; asm("fma.rn.f32x2 %0, %1, %2, %3;" : "=l"(d) : "l"(a), "l"(b), "l"(c)); return d;
}
__device__ __forceinline__ u64c mul2(u64c a, u64c b) {
    u64c d; asm("mul.rn.f32x2 %0, %1, %2;" : "=l"(d) : "l"(a), "l"(b)); return d;
}
__device__ __forceinline__ float hadd2(u64c a) {
    float lo, hi; asm("mov.b64 {%0, %1}, %2;" : "=f"(lo), "=f"(hi) : "l"(a)); return lo + hi;
}

// ---------------- transpose Wq/Wk/Wout ----------------
__global__ void transpose_k(const float* __restrict__ Wq,
                            const float* __restrict__ Wk,
                            const float* __restrict__ Wo) {
    __shared__ float tb[32][33];
    const float* src = blockIdx.z == 0 ? Wq : (blockIdx.z == 1 ? Wk : Wo);
    float* dst = blockIdx.z == 0 ? g_WqT : (blockIdx.z == 1 ? g_WkT : g_WoT);
    int tx = threadIdx.x, ty = threadIdx.y;
    int bx = blockIdx.x * 32, by = blockIdx.y * 32;
#pragma unroll
    for (int j = 0; j < 32; j += 8) tb[ty + j][tx] = src[(by + ty + j) * DD + bx + tx];
    __syncthreads();
#pragma unroll
    for (int j = 0; j < 32; j += 8) dst[(bx + ty + j) * DD + by + tx] = tb[tx][ty + j];
}

// ---------------- prepass ----------------
__global__ __launch_bounds__(DD)
void prepass_kernel(const float* __restrict__ x,
                    const float* __restrict__ P0,
                    const float* __restrict__ log_gain,
                    const float* __restrict__ coeffs) {
    const int b = blockIdx.y, l0 = blockIdx.x * TL;
    const int e = threadIdx.x;
    __shared__ float xs[TL][DD];
    __shared__ float qs[TL][DD];
    __shared__ float rn[TL];

    const float* xp = x + (b * LL + l0) * DD;
#pragma unroll
    for (int tt = 0; tt < TL; ++tt) xs[tt][e] = xp[tt * DD + e];
    __syncthreads();

    float qa[TL], ka[TL];
#pragma unroll
    for (int tt = 0; tt < TL; ++tt) { qa[tt] = 0.f; ka[tt] = 0.f; }
    for (int d = 0; d < DD; ++d) {
        float wq = g_WqT[d * DD + e], wk = g_WkT[d * DD + e];
#pragma unroll
        for (int tt = 0; tt < TL; ++tt) {
            float xv = xs[tt][d];
            qa[tt] += xv * wq;
            ka[tt] += xv * wk;
        }
    }
#pragma unroll
    for (int tt = 0; tt < TL; ++tt) qs[tt][e] = qa[tt];
    __syncthreads();
#pragma unroll
    for (int tt = 0; tt < TL; ++tt) xs[tt][e] = ka[tt] * ka[tt];
    __syncthreads();
    {
        const int w = e >> 5, l = e & 31;
#pragma unroll
        for (int i = 0; i < 4; ++i) {
            int tt = w * 4 + i;
            float v = xs[tt][l] + xs[tt][l + 32] + xs[tt][l + 64] + xs[tt][l + 96];
#pragma unroll
            for (int o = 16; o; o >>= 1) v += __shfl_xor_sync(0xffffffffu, v, o);
            if (l == 0) rn[tt] = 1.0f / fmaxf(sqrtf(v), EPSN);
        }
    }
    __syncthreads();

    float qp[TL];
#pragma unroll
    for (int tt = 0; tt < TL; ++tt) qp[tt] = 0.f;
    for (int d = 0; d < DD; ++d) {
        float p = P0[d * DD + e];
#pragma unroll
        for (int tt = 0; tt < TL; ++tt) qp[tt] += qs[tt][d] * p;
    }
    const float gain = expf(log_gain[e]);
    const float c0 = coeffs[0], c1 = coeffs[1];
#pragma unroll
    for (int tt = 0; tt < TL; ++tt) {
        float kn = ka[tt] * rn[tt];
        g_kphi[(b * LL + l0 + tt) * DD + e] = c0 * kn + c1 * kn * kn;
        float qv = tanhf(gain * qp[tt]);
        g_qphi[(b * LL + l0 + tt) * DD + e] = c0 * qv + c1 * qv * qv;
    }
}

// ---------------- postpass ----------------
__global__ __launch_bounds__(DD)
void postpass_kernel(const float* __restrict__ bout, float* __restrict__ out) {
    const int b = blockIdx.y, l0 = blockIdx.x * TL;
    const int e = threadIdx.x;
    __shared__ float ys[TL][DD];
#pragma unroll
    for (int tt = 0; tt < TL; ++tt) ys[tt][e] = g_y[(b * LL + l0 + tt) * DD + e];
    __syncthreads();
    float acc[TL];
#pragma unroll
    for (int tt = 0; tt < TL; ++tt) acc[tt] = 0.f;
    for (int d = 0; d < DD; ++d) {
        float w = g_WoT[d * DD + e];
#pragma unroll
        for (int tt = 0; tt < TL; ++tt) acc[tt] += ys[tt][d] * w;
    }
    const float bo = bout[e];
#pragma unroll
    for (int tt = 0; tt < TL; ++tt) out[(b * LL + l0 + tt) * DD + e] = acc[tt] + bo;
}

// ---------------- scan: rank-structured recurrence, 4-CTA cluster ----------------
// smem float offsets
#define OFF_S   0                          // 32*PP
#define OFF_Tm  (32*PP)                    // 32*PP
#define OFF_S0  (64*PP)                    // 128*PP (init only)
#define OFF_EB  (64*PP + 128*PP)           // [2][128]
#define OFF_VB  (OFF_EB + 256)
#define OFF_WP  (OFF_VB + 256)             // [2][4][128]
#define OFF_ZP  (OFF_WP + 1024)
#define OFF_WA  (OFF_ZP + 1024)            // [128]
#define OFF_ZA  (OFF_WA + 128)
#define OFF_UP2 (OFF_ZA + 128)             // [32][9] u2 partials (local, T-symmetric)
#define OFF_KB  (OFF_UP2 + 288)            // [2][128]
#define OFF_QS  (OFF_KB + 256)
#define OFF_XN  (OFF_QS + 128)             // [2][128]
#define OFF_YP  (OFF_XN + 256)             // [32][9]
#define OFF_PR  (OFF_YP + 288)
#define OFF_VP  (OFF_PR + 288)
#define OFF_EN  (OFF_VP + 288)             // [32]
#define OFF_VNL (OFF_EN + 32)
#define OFF_SC  (OFF_VNL + 32)
#define SCAN_FLOATS (OFF_SC + 8)
#define SCAN_SMEM (SCAN_FLOATS * 4)

// packed pair update: 15 f32x2 ops per 2 elements
#define UPD2(SX, TX, KX, EX, VX, WX, ZX, QX, NX, idx) { \
    u64c Sn = fma2(cA1, SX, mul2(er2, KX)); \
    u64c Tn = fma2(cA2, TX, fma2(al2, EX, mul2(be2, VX))); \
    u64c Un = fma2(cA3, u8[idx], fma2(pr2, KX, fma2(cw2, WX, mul2(cz2, ZX)))); \
    u8[idx] = Un; \
    u64c Mn = fma2(c99, m8[idx], fma2(ncS2, Sn, mul2(cU2, Un))); \
    m8[idx] = Mn; \
    accY2 = fma2(Mn, QX, accY2); \
    accP2 = fma2(Mn, NX, accP2); \
    accV2 = fma2(Sn, NX, accV2); \
    SX = Sn; TX = Tn; }

__global__ __launch_bounds__(256, 1)
void scan_kernel(const float* __restrict__ x,
                 const float* __restrict__ M0,
                 const float* __restrict__ S0) {
    extern __shared__ float sm[];
    float* Ss   = sm + OFF_S;
    float* Ts   = sm + OFF_Tm;
    float* S0s  = sm + OFF_S0;
    float* eb   = sm + OFF_EB;
    float* vbuf = sm + OFF_VB;
    float* wa   = sm + OFF_WA;
    float* za   = sm + OFF_ZA;
    float* up2  = sm + OFF_UP2;
    float* kb   = sm + OFF_KB;
    float* qs   = sm + OFF_QS;
    float* xn   = sm + OFF_XN;
    float* yp   = sm + OFF_YP;
    float* prp  = sm + OFF_PR;
    float* vp   = sm + OFF_VP;
    float* en   = sm + OFF_EN;
    float* vnl  = sm + OFF_VNL;
    float* sc   = sm + OFF_SC;

    const uint32_t sbase = smem_u32(sm);
    const int tid = threadIdx.x;
    const int lane = tid & 31;           // owned local row
    const int cg = tid >> 5;             // 16-col group
    const int c0 = cg * 16;
    const uint32_t rk = cluster_rank();
    const int batch = blockIdx.x >> 2;
    const int rbase = (int)rk * RK;

    uint32_t pb[4];
#pragma unroll
    for (int i = 0; i < 4; ++i)
        asm("mapa.shared::cluster.u32 %0, %1, %2;" : "=r"(pb[i]) : "r"(sbase), "r"(i));

    const float* kphi = g_kphi + batch * LL * DD;
    const float* qphi = g_qphi + batch * LL * DD;
    const float* xb = x + batch * LL * DD;
    float* yb = g_y + batch * LL * DD;

    const u64c cA1 = pk2(A1, A1), cA2 = pk2(A2, A2), cA3 = pk2(A3, A3), c99 = pk2(0.99f, 0.99f);

    // ---------- init ----------
    for (int i = tid; i < DD * DD; i += 256) {
        int r = i >> 7, c = i & 127;
        S0s[r * PP + c] = S0[i];
    }
    if (tid < DD) {
        kb[tid] = kphi[tid];             // k_0
        kb[DD + tid] = kphi[DD + tid];   // k_1
        qs[tid] = qphi[tid];             // q_0
        xn[tid] = xb[DD + tid];          // x_1 (slot p=0)
    }
    float mi[16], ui[16];
#pragma unroll
    for (int j = 0; j < 16; ++j) mi[j] = M0[(rbase + lane) * DD + c0 + j];
    __syncthreads();

    // sigma0 (deterministic fixed-order reduce)
    {
        float ps = 0.f;
        for (int i = tid; i < DD * DD; i += 256) {
            int r = i >> 7, c = i & 127;
            float v = S0s[r * PP + c];
            ps += v * v;
        }
        prp[tid] = ps;
    }
    __syncthreads();
    if (tid < 32) {
        float s = 0.f;
#pragma unroll
        for (int j = 0; j < 8; ++j) s += prp[tid * 8 + j];
#pragma unroll
        for (int o = 16; o; o >>= 1) s += __shfl_xor_sync(0xffffffffu, s, o);
        if (tid == 0) sc[3] = s;
    }
    __syncthreads();
    float sig = sc[3];

    // S strip
    for (int i = tid; i < RK * DD; i += 256) {
        int r = i >> 7, c = i & 127;
        Ss[r * PP + c] = S0s[(rbase + r) * PP + c];
    }
    __syncthreads();
    // T strip + U regs
    if (sig != 0.0f) {
#pragma unroll 1
        for (int j = 0; j < 16; ++j) {
            int c = c0 + j;
            float a = 0.f;
            for (int k = 0; k < DD; ++k)
                a += S0s[(rbase + lane) * PP + k] * S0s[c * PP + k];
            Ts[lane * PP + c] = a;
        }
        __syncthreads();
#pragma unroll 1
        for (int j = 0; j < 16; ++j) {
            int c = c0 + j;
            float a = 0.f;
            for (int k = 0; k < DD; ++k)
                a += Ts[lane * PP + k] * S0s[k * PP + c];
            ui[j] = a;
        }
    } else {
        for (int i = tid; i < RK * DD; i += 256) {
            int r = i >> 7, c = i & 127;
            Ts[r * PP + c] = 0.f;
        }
#pragma unroll
        for (int j = 0; j < 16; ++j) ui[j] = 0.f;
    }
    __syncthreads();

    // e0 = M0 k0 - x0 ; v0 = S0 k0 (strip partials, pitch-9 scratch)
    {
        float pr = 0.f, vv = 0.f;
        const int base = lane * PP + c0;
#pragma unroll
        for (int j = 0; j < 16; ++j) {
            float kc = kb[c0 + j];
            pr += mi[j] * kc;
            vv += Ss[base + j] * kc;
        }
        prp[lane * 9 + cg] = pr;
        vp[lane * 9 + cg] = vv;
    }
    // pack M/U state
    u64c m8[8], u8[8];
#pragma unroll
    for (int j = 0; j < 8; ++j) {
        m8[j] = pk2(mi[2 * j], mi[2 * j + 1]);
        u8[j] = pk2(ui[2 * j], ui[2 * j + 1]);
    }
    __syncthreads();
    if (tid < 32) {
        float s = 0.f;
#pragma unroll
        for (int j = 0; j < 8; ++j) s += prp[tid * 9 + j];
        float e = s - xb[rbase + tid];
        en[tid] = e;
        uint32_t eo = (OFF_EB + rbase + tid) * 4;
#pragma unroll
        for (int i = 0; i < 4; ++i) pst(pb[i] + eo, e);
    } else if (tid < 64) {
        int i2 = tid - 32;
        float s = 0.f;
#pragma unroll
        for (int j = 0; j < 8; ++j) s += vp[i2 * 9 + j];
        vnl[i2] = s;
        uint32_t vo = (OFF_VB + rbase + i2) * 4;
#pragma unroll
        for (int i = 0; i < 4; ++i) pst(pb[i] + vo, s);
    }
    __syncthreads();
    // w0/z0 column partials — conflict-free (1 thread/col)
    if (tid < 128) {
        int c = tid;
        float wv = 0.f, zv = 0.f;
#pragma unroll 8
        for (int r = 0; r < 32; ++r) {
            float s = Ss[r * PP + c];
            wv += s * en[r];
            zv += s * vnl[r];
        }
        uint32_t wo = (OFF_WP + (int)rk * 128 + c) * 4;
        uint32_t zo = (OFF_ZP + (int)rk * 128 + c) * 4;
#pragma unroll
        for (int i = 0; i < 4; ++i) { pst(pb[i] + wo, wv); pst(pb[i] + zo, zv); }
    }
    CARRIVE();

    // ---------- main loop ----------
    for (int t = 0; t < LL; ++t) {
        const int p = t & 1;
        float rq = 0.f, rx = 0.f, rkk = 0.f;
        if (tid >= 128) {   // prefetch (upper half); latency hides under CWAIT
            int i2 = tid - 128;
            int t1 = (t + 1 < LL) ? t + 1 : LL - 1;
            int t2 = (t + 2 < LL) ? t + 2 : LL - 1;
            rq = qphi[t1 * DD + i2];
            rx = xb[t2 * DD + i2];
            rkk = kphi[t2 * DD + i2];
        }
        CWAIT();

        // phase 1a: assemble w/z from 4 CTA partials (one item/thread)
        {
            int c = tid & 127;
            int srco = (tid < 128 ? OFF_WP : OFF_ZP) + p * 512 + c;
            float s = sm[srco] + sm[srco + 128] + sm[srco + 256] + sm[srco + 384];
            sm[(tid < 128 ? OFF_WA : OFF_ZA) + c] = s;
        }
        // phase 1b: u2 partials from local T strip (T symmetric: u2 = T e), packed
        {
            const float* ecur = eb + p * DD;
            u64c s2 = pk2(0.f, 0.f);
            const int base = lane * PP + c0;
#pragma unroll
            for (int j4 = 0; j4 < 4; ++j4) {
                ulonglong2 t2v = *(const ulonglong2*)&Ts[base + j4 * 4];
                ulonglong2 e2v = *(const ulonglong2*)&ecur[c0 + j4 * 4];
                s2 = fma2(t2v.x, e2v.x, s2);
                s2 = fma2(t2v.y, e2v.y, s2);
            }
            up2[lane * 9 + cg] = hadd2(s2);
        }
        // phase 1c: scalars kappa, eps, nu
        if (cg < 3) {
            const float* va = (cg == 0) ? (kb + p * DD) : (eb + p * DD);
            const float* vb2 = (cg == 2) ? (vbuf + p * DD) : va;
            float s = 0.f;
#pragma unroll
            for (int i2 = 0; i2 < 4; ++i2) { int idx = lane + i2 * 32; s += va[idx] * vb2[idx]; }
#pragma unroll
            for (int o = 16; o; o >>= 1) s += __shfl_xor_sync(0xffffffffu, s, o);
            if (lane == 0) sc[cg] = s;
        }
        __syncthreads();

        const float kappa = sc[0], eps = sc[1], nu = sc[2];
        sig = A2 * sig + 2.0f * A1 * nu + kappa * eps;
        const float nrm = sqrtf(sig) + 1e-6f;
        const float cS = 0.015f / nrm;
        const float cU = 0.005f / (nrm * nrm * nrm);

        // phase 2: fused strip update (packed f32x2) + partials
        {
            const float e_r = eb[p * DD + rbase + lane];
            const float v_r = vbuf[p * DD + rbase + lane];
            float u2r = up2[lane * 9 + 0] + up2[lane * 9 + 1] + up2[lane * 9 + 2] + up2[lane * 9 + 3]
                      + up2[lane * 9 + 4] + up2[lane * 9 + 5] + up2[lane * 9 + 6] + up2[lane * 9 + 7];
            const float alpha = A1 * v_r + kappa * e_r;
            const float beta = A1 * e_r;
            const float p_r = A2 * u2r + A1 * eps * v_r + (A1 * nu + kappa * eps) * e_r;
            const float cwv = A2 * v_r + A1 * kappa * e_r;
            const float czv = A2 * e_r;
            const u64c er2 = pk2(e_r, e_r);
            const u64c al2 = pk2(alpha, alpha);
            const u64c be2 = pk2(beta, beta);
            const u64c pr2 = pk2(p_r, p_r);
            const u64c cw2 = pk2(cwv, cwv);
            const u64c cz2 = pk2(czv, czv);
            const u64c ncS2 = pk2(-cS, -cS);
            const u64c cU2 = pk2(cU, cU);
            const float* kcur = kb + p * DD;
            const float* knxp = kb + (p ^ 1) * DD;
            const float* ecol = eb + p * DD;
            const float* vcol = vbuf + p * DD;
            u64c accY2 = pk2(0.f, 0.f), accP2 = accY2, accV2 = accY2;
            const int base = lane * PP + c0;
#pragma unroll
            for (int j4 = 0; j4 < 4; ++j4) {
                const int c = c0 + j4 * 4;
                ulonglong2 kc2 = *(const ulonglong2*)&kcur[c];
                ulonglong2 ec2 = *(const ulonglong2*)&ecol[c];
                ulonglong2 vc2 = *(const ulonglong2*)&vcol[c];
                ulonglong2 wc2 = *(const ulonglong2*)&wa[c];
                ulonglong2 zc2 = *(const ulonglong2*)&za[c];
                ulonglong2 qc2 = *(const ulonglong2*)&qs[c];
                ulonglong2 kn2 = *(const ulonglong2*)&knxp[c];
                ulonglong2 S2 = *(ulonglong2*)&Ss[base + j4 * 4];
                ulonglong2 T2 = *(ulonglong2*)&Ts[base + j4 * 4];
                UPD2(S2.x, T2.x, kc2.x, ec2.x, vc2.x, wc2.x, zc2.x, qc2.x, kn2.x, j4 * 2 + 0)
                UPD2(S2.y, T2.y, kc2.y, ec2.y, vc2.y, wc2.y, zc2.y, qc2.y, kn2.y, j4 * 2 + 1)
                *(ulonglong2*)&Ss[base + j4 * 4] = S2;
                *(ulonglong2*)&Ts[base + j4 * 4] = T2;
            }
            yp[lane * 9 + cg] = hadd2(accY2);
            prp[lane * 9 + cg] = hadd2(accP2);
            vp[lane * 9 + cg] = hadd2(accV2);
        }
        __syncthreads();

        // phase 3: reductions + peer exchange of e,v
        if (tid < 32) {
            float s = 0.f;
#pragma unroll
            for (int j = 0; j < 8; ++j) s += yp[tid * 9 + j];
            yb[t * DD + rbase + tid] = s;
        } else if (tid < 64) {
            int i2 = tid - 32;
            float s = 0.f;
#pragma unroll
            for (int j = 0; j < 8; ++j) s += prp[i2 * 9 + j];
            float e = s - xn[p * DD + rbase + i2];
            en[i2] = e;
            if (t + 1 < LL) {
                uint32_t eo = (OFF_EB + (p ^ 1) * DD + rbase + i2) * 4;
#pragma unroll
                for (int i = 0; i < 4; ++i) pst(pb[i] + eo, e);
            }
        } else if (tid < 96) {
            int i2 = tid - 64;
            float s = 0.f;
#pragma unroll
            for (int j = 0; j < 8; ++j) s += vp[i2 * 9 + j];
            vnl[i2] = s;
            if (t + 1 < LL) {
                uint32_t vo = (OFF_VB + (p ^ 1) * DD + rbase + i2) * 4;
#pragma unroll
                for (int i = 0; i < 4; ++i) pst(pb[i] + vo, s);
            }
        }
        __syncthreads();

        // phase 4: conflict-free w/z column partials + staging + exchange
        if (t + 1 < LL) {
            if (tid < 128) {
                int c = tid;
                float wv = 0.f, zv = 0.f;
#pragma unroll 8
                for (int r = 0; r < 32; ++r) {
                    float s = Ss[r * PP + c];
                    wv += s * en[r];
                    zv += s * vnl[r];
                }
                uint32_t wo = (OFF_WP + (p ^ 1) * 512 + (int)rk * 128 + c) * 4;
                uint32_t zo = (OFF_ZP + (p ^ 1) * 512 + (int)rk * 128 + c) * 4;
#pragma unroll
                for (int i = 0; i < 4; ++i) { pst(pb[i] + wo, wv); pst(pb[i] + zo, zv); }
            } else {
                int c = tid - 128;
                qs[c] = rq;
                xn[(p ^ 1) * DD + c] = rx;
                kb[p * DD + c] = rkk;
            }
            CARRIVE();
        }
    }
}

// ---------------- harness entry ----------------
extern "C" void kernel_launch(void* const* d_in, const int* in_sizes, int n_in,
                              void* d_out, int out_size) {
    const float* x    = (const float*)d_in[0];
    const float* Wq   = (const float*)d_in[1];
    const float* Wk   = (const float*)d_in[2];
    const float* P0   = (const float*)d_in[3];
    const float* M0   = (const float*)d_in[4];
    const float* S0   = (const float*)d_in[5];
    const float* lg   = (const float*)d_in[6];
    const float* cf   = (const float*)d_in[7];
    const float* Wout = (const float*)d_in[8];
    const float* bout = (const float*)d_in[9];
    float* out = (float*)d_out;

    cudaFuncSetAttribute(scan_kernel, cudaFuncAttributeMaxDynamicSharedMemorySize, SCAN_SMEM);

    transpose_k<<<dim3(4, 4, 3), dim3(32, 8)>>>(Wq, Wk, Wout);
    prepass_kernel<<<dim3(LL / TL, BB), DD>>>(x, P0, lg, cf);

    cudaLaunchConfig_t cfg = {};
    cfg.gridDim = dim3(CS * BB, 1, 1);
    cfg.blockDim = dim3(256, 1, 1);
    cfg.dynamicSmemBytes = SCAN_SMEM;
    cfg.stream = 0;
    cudaLaunchAttribute attrs[1];
    attrs[0].id = cudaLaunchAttributeClusterDimension;
    attrs[0].val.clusterDim.x = CS;
    attrs[0].val.clusterDim.y = 1;
    attrs[0].val.clusterDim.z = 1;
    cfg.attrs = attrs;
    cfg.numAttrs = 1;
    cudaLaunchKernelEx(&cfg, scan_kernel, x, M0, S0);

    postpass_kernel<<<dim3(LL / TL, BB), DD>>>(bout, out);
}